// round 10
// baseline (speedup 1.0000x reference)
#include <cuda_runtime.h>
#include <math.h>
#include <stdint.h>

// ---------------- model constants ----------------
#define Lc   12
#define Hc   768
#define NHc  12
#define DNc  32
#define DRc  32
#define DVc  64
#define Rc   512
#define Ec   8
#define KTOP 2
#define Ic   256
#define SIc  1024
#define Bc   2
#define Sc   512
#define Tc   (Bc*Sc)
#define QD   (DNc+DRc)        // 64
#define KVD  (DNc+DVc)        // 96
#define KVAW (Rc+DRc)         // 544

// ---------------- scratch (device globals, no allocation) ----------------
__device__ float g_h   [Tc*Hc];
__device__ float g_x   [Tc*Hc];
__device__ float g_q   [Tc*(NHc*QD)];
__device__ float g_kva [Tc*KVAW];
__device__ float g_ckv [Tc*Rc];
__device__ float g_kv  [Tc*(NHc*KVD)];
__device__ float g_attn[Tc*Hc];
__device__ float g_t1  [Tc*SIc];
__device__ float g_mg  [Ec*Tc*Ic];
__device__ float g_eo  [Tc*2*Hc];
__device__ int   g_list[Ec*Tc];
__device__ int   g_cnt [Ec];
__device__ float g_topw[Tc*KTOP];

// ---------------- helpers ----------------
__device__ __forceinline__ float warpsum(float v) {
    #pragma unroll
    for (int o = 16; o; o >>= 1) v += __shfl_down_sync(0xffffffffu, v, o);
    return v;
}

__device__ __forceinline__ uint32_t f2tf(float x) {
    uint32_t u;
    asm("cvt.rna.tf32.f32 %0, %1;" : "=r"(u) : "f"(x));
    return u;
}

#define MMA_TF32(d, a0, a1, a2, a3, b0, b1) \
    asm volatile("mma.sync.aligned.m16n8k8.row.col.f32.tf32.tf32.f32 " \
        "{%0,%1,%2,%3}, {%4,%5,%6,%7}, {%8,%9}, {%0,%1,%2,%3};" \
        : "+f"((d)[0]), "+f"((d)[1]), "+f"((d)[2]), "+f"((d)[3]) \
        : "r"(a0), "r"(a1), "r"(a2), "r"(a3), "r"(b0), "r"(b1))

// ---------------- tensor-core 3xtf32 GEMM (64x64 CTA tile, 128 thr) ----------------
// 4 warps, warp tile 32x32 (warpM = wid&1, warpN = wid>>1).
// Operands are tf-split ONCE at SMEM store time into hi/lo buffers; the
// mainloop is pure LDS + MMA. Non-dual modes double-buffer fragments in
// registers to hide LDS latency behind MMA issue.
// MODE 0: dense (+bias, +accum)
// MODE 1: dual silu: C = silu(A@B1^T) * (A@B3^T)
// MODE 2: moe1: A rows gathered via g_list[e], dual+silu -> g_mg[e]
// MODE 3: moe2: A = g_mg[e], scatter rows to g_eo via g_list * g_topw
#define LDW  36
#define ASZ_W (64*LDW)        // 2304 words per A buffer

template<int MODE>
__global__ __launch_bounds__(128) void mma_gemm_kernel(
    const float* __restrict__ A, const float* __restrict__ B1w,
    const float* __restrict__ B3w, const float* __restrict__ bias,
    float* __restrict__ C, int M, int N, int Kd, int accum)
{
    constexpr bool DUAL  = (MODE == 1 || MODE == 2);
    constexpr int  BROWS = DUAL ? 128 : 64;
    constexpr int  BSZ_W = BROWS * LDW;
    constexpr int  NB    = DUAL ? 8 : 4;

    int tid = threadIdx.x;
    int wid = tid >> 5, lane = tid & 31;
    int g = lane >> 2, tg = lane & 3;
    int warpM = wid & 1, warpN = wid >> 1;

    int e   = (MODE >= 2) ? blockIdx.z : 0;
    int cnt = (MODE >= 2) ? g_cnt[e] : M;
    int row0 = blockIdx.y * 64;
    if (row0 >= cnt) return;
    int col0 = blockIdx.x * 64;

    const float* Ap  = A;
    const float* B1p = B1w;
    const float* B3p = B3w;
    float* Cp = C;
    if (MODE == 2) {
        B1p = B1w + (size_t)e * Ic * Hc;
        B3p = B3w + (size_t)e * Ic * Hc;
        Cp  = C + (size_t)e * Tc * Ic;
    }
    if (MODE == 3) {
        Ap  = A + (size_t)e * Tc * Ic;
        B1p = B1w + (size_t)e * Hc * Ic;
    }

    extern __shared__ float dsm[];
    float* AHI = dsm;                         // [2][ASZ_W]
    float* ALO = dsm + 2 * ASZ_W;             // [2][ASZ_W]
    float* BHI = dsm + 4 * ASZ_W;             // [2][BSZ_W]
    float* BLO = dsm + 4 * ASZ_W + 2 * BSZ_W; // [2][BSZ_W]
    __shared__ int s_tok[64];

    if (MODE == 2) {
        if (tid < 64) {
            int grow = row0 + tid;
            int tok2 = (grow < cnt) ? g_list[e * Tc + grow] : 0;
            s_tok[tid] = tok2 >> 1;
        }
        __syncthreads();
    }

    int lc4 = tid & 7;           // float4 column 0..7
    int lrb = tid >> 3;          // base row 0..15

    int nchunks = Kd / 32;

    float4 stA[4], stB[NB];

    auto ldStage = [&](int ch) {
        int c0 = ch * 32 + lc4 * 4;
        #pragma unroll
        for (int i = 0; i < 4; i++) {
            int r = lrb + i * 16;
            const float* src = (MODE == 2) ? &g_x[(size_t)s_tok[r] * Hc + c0]
                                           : Ap + (size_t)(row0 + r) * Kd + c0;
            stA[i] = *(const float4*)src;
        }
        #pragma unroll
        for (int i = 0; i < NB; i++) {
            int r = lrb + i * 16;
            int gn; const float* base;
            if (!DUAL) { gn = col0 + r; base = B1p; }
            else if (r < 64) { gn = col0 + r; base = B1p; }
            else { gn = col0 + r - 64; base = B3p; }
            stB[i] = (gn < N) ? *(const float4*)(base + (size_t)gn * Kd + c0)
                              : make_float4(0.f, 0.f, 0.f, 0.f);
        }
    };

    auto stStage = [&](int buf) {
        #pragma unroll
        for (int i = 0; i < 4; i++) {
            int r = lrb + i * 16;
            int w = r * LDW + lc4 * 4;
            float4 v = stA[i];
            uint32_t h0 = f2tf(v.x), h1 = f2tf(v.y), h2 = f2tf(v.z), h3 = f2tf(v.w);
            float4 hi = make_float4(__uint_as_float(h0), __uint_as_float(h1),
                                    __uint_as_float(h2), __uint_as_float(h3));
            float4 lo = make_float4(__uint_as_float(f2tf(v.x - hi.x)),
                                    __uint_as_float(f2tf(v.y - hi.y)),
                                    __uint_as_float(f2tf(v.z - hi.z)),
                                    __uint_as_float(f2tf(v.w - hi.w)));
            *(float4*)&AHI[buf * ASZ_W + w] = hi;
            *(float4*)&ALO[buf * ASZ_W + w] = lo;
        }
        #pragma unroll
        for (int i = 0; i < NB; i++) {
            int r = lrb + i * 16;
            int w = r * LDW + lc4 * 4;
            float4 v = stB[i];
            uint32_t h0 = f2tf(v.x), h1 = f2tf(v.y), h2 = f2tf(v.z), h3 = f2tf(v.w);
            float4 hi = make_float4(__uint_as_float(h0), __uint_as_float(h1),
                                    __uint_as_float(h2), __uint_as_float(h3));
            float4 lo = make_float4(__uint_as_float(f2tf(v.x - hi.x)),
                                    __uint_as_float(f2tf(v.y - hi.y)),
                                    __uint_as_float(f2tf(v.z - hi.z)),
                                    __uint_as_float(f2tf(v.w - hi.w)));
            *(float4*)&BHI[buf * BSZ_W + w] = hi;
            *(float4*)&BLO[buf * BSZ_W + w] = lo;
        }
    };

    // prologue: chunk 0 -> smem buf0; chunk 1 -> regs
    ldStage(0);
    stStage(0);
    if (nchunks > 1) ldStage(1);
    __syncthreads();

    float d1[2][4][4];
    float d3[DUAL ? 2 : 1][DUAL ? 4 : 1][4];
    #pragma unroll
    for (int m = 0; m < 2; m++)
        #pragma unroll
        for (int j = 0; j < 4; j++)
            #pragma unroll
            for (int q = 0; q < 4; q++) {
                d1[m][j][q] = 0.f;
                if (DUAL) d3[m][j][q] = 0.f;
            }

    for (int c = 0; c < nchunks; c++) {
        int buf = c & 1;

        const float* AbH = AHI + buf * ASZ_W + (warpM * 32) * LDW;
        const float* AbL = ALO + buf * ASZ_W + (warpM * 32) * LDW;
        const float* BbH = BHI + buf * BSZ_W + (warpN * 32) * LDW;
        const float* BbL = BLO + buf * BSZ_W + (warpN * 32) * LDW;
        const float* Bb3H = BbH + 64 * LDW;   // valid only in DUAL
        const float* Bb3L = BbL + 64 * LDW;

        if (!DUAL) {
            // fragment double-buffering: prefetch ks+1 while ks MMAs drain
            uint32_t fa[2][16], fb[2][16];
            auto ldfrag = [&](int ks, int s) {
                int kc = ks * 8 + tg;
                #pragma unroll
                for (int m = 0; m < 2; m++) {
                    const float* apH = AbH + (m * 16 + g) * LDW;
                    const float* apL = AbL + (m * 16 + g) * LDW;
                    fa[s][m * 8 + 0] = __float_as_uint(apH[kc]);
                    fa[s][m * 8 + 1] = __float_as_uint(apH[8 * LDW + kc]);
                    fa[s][m * 8 + 2] = __float_as_uint(apH[kc + 4]);
                    fa[s][m * 8 + 3] = __float_as_uint(apH[8 * LDW + kc + 4]);
                    fa[s][m * 8 + 4] = __float_as_uint(apL[kc]);
                    fa[s][m * 8 + 5] = __float_as_uint(apL[8 * LDW + kc]);
                    fa[s][m * 8 + 6] = __float_as_uint(apL[kc + 4]);
                    fa[s][m * 8 + 7] = __float_as_uint(apL[8 * LDW + kc + 4]);
                }
                #pragma unroll
                for (int j = 0; j < 4; j++) {
                    const float* bpH = BbH + (j * 8 + g) * LDW;
                    const float* bpL = BbL + (j * 8 + g) * LDW;
                    fb[s][j * 4 + 0] = __float_as_uint(bpH[kc]);
                    fb[s][j * 4 + 1] = __float_as_uint(bpH[kc + 4]);
                    fb[s][j * 4 + 2] = __float_as_uint(bpL[kc]);
                    fb[s][j * 4 + 3] = __float_as_uint(bpL[kc + 4]);
                }
            };
            ldfrag(0, 0);
            // overlap global staging for future chunks with MMA work
            if (c + 1 < nchunks) stStage(buf ^ 1);
            if (c + 2 < nchunks) ldStage(c + 2);
            #pragma unroll
            for (int ks = 0; ks < 4; ks++) {
                int cur = ks & 1;
                if (ks < 3) ldfrag(ks + 1, cur ^ 1);
                #pragma unroll
                for (int j = 0; j < 4; j++) {
                    #pragma unroll
                    for (int m = 0; m < 2; m++) {
                        MMA_TF32(d1[m][j], fa[cur][m*8+0], fa[cur][m*8+1], fa[cur][m*8+2], fa[cur][m*8+3],
                                 fb[cur][j*4+0], fb[cur][j*4+1]);
                        MMA_TF32(d1[m][j], fa[cur][m*8+4], fa[cur][m*8+5], fa[cur][m*8+6], fa[cur][m*8+7],
                                 fb[cur][j*4+0], fb[cur][j*4+1]);
                        MMA_TF32(d1[m][j], fa[cur][m*8+0], fa[cur][m*8+1], fa[cur][m*8+2], fa[cur][m*8+3],
                                 fb[cur][j*4+2], fb[cur][j*4+3]);
                    }
                }
            }
        } else {
            if (c + 1 < nchunks) stStage(buf ^ 1);
            if (c + 2 < nchunks) ldStage(c + 2);
            #pragma unroll
            for (int ks = 0; ks < 4; ks++) {
                int kc = ks * 8 + tg;
                uint32_t ah[2][4], al[2][4];
                #pragma unroll
                for (int m = 0; m < 2; m++) {
                    const float* apH = AbH + (m * 16 + g) * LDW;
                    const float* apL = AbL + (m * 16 + g) * LDW;
                    ah[m][0] = __float_as_uint(apH[kc]);
                    ah[m][1] = __float_as_uint(apH[8 * LDW + kc]);
                    ah[m][2] = __float_as_uint(apH[kc + 4]);
                    ah[m][3] = __float_as_uint(apH[8 * LDW + kc + 4]);
                    al[m][0] = __float_as_uint(apL[kc]);
                    al[m][1] = __float_as_uint(apL[8 * LDW + kc]);
                    al[m][2] = __float_as_uint(apL[kc + 4]);
                    al[m][3] = __float_as_uint(apL[8 * LDW + kc + 4]);
                }
                #pragma unroll
                for (int j = 0; j < 4; j++) {
                    const float* bpH = BbH + (j * 8 + g) * LDW;
                    const float* bpL = BbL + (j * 8 + g) * LDW;
                    uint32_t bh0 = __float_as_uint(bpH[kc]);
                    uint32_t bh1 = __float_as_uint(bpH[kc + 4]);
                    uint32_t bl0 = __float_as_uint(bpL[kc]);
                    uint32_t bl1 = __float_as_uint(bpL[kc + 4]);
                    #pragma unroll
                    for (int m = 0; m < 2; m++) {
                        MMA_TF32(d1[m][j], ah[m][0], ah[m][1], ah[m][2], ah[m][3], bh0, bh1);
                        MMA_TF32(d1[m][j], al[m][0], al[m][1], al[m][2], al[m][3], bh0, bh1);
                        MMA_TF32(d1[m][j], ah[m][0], ah[m][1], ah[m][2], ah[m][3], bl0, bl1);
                    }
                }
                #pragma unroll
                for (int j = 0; j < 4; j++) {
                    const float* bpH = Bb3H + (j * 8 + g) * LDW;
                    const float* bpL = Bb3L + (j * 8 + g) * LDW;
                    uint32_t bh0 = __float_as_uint(bpH[kc]);
                    uint32_t bh1 = __float_as_uint(bpH[kc + 4]);
                    uint32_t bl0 = __float_as_uint(bpL[kc]);
                    uint32_t bl1 = __float_as_uint(bpL[kc + 4]);
                    #pragma unroll
                    for (int m = 0; m < 2; m++) {
                        MMA_TF32(d3[m][j], ah[m][0], ah[m][1], ah[m][2], ah[m][3], bh0, bh1);
                        MMA_TF32(d3[m][j], al[m][0], al[m][1], al[m][2], al[m][3], bh0, bh1);
                        MMA_TF32(d3[m][j], ah[m][0], ah[m][1], ah[m][2], ah[m][3], bl0, bl1);
                    }
                }
            }
        }
        __syncthreads();
    }

    // ---- epilogue ----
    int rbase = row0 + warpM * 32;
    int cbase = col0 + warpN * 32;

    #pragma unroll
    for (int m = 0; m < 2; m++) {
        #pragma unroll
        for (int j = 0; j < 4; j++) {
            int col = cbase + j * 8 + tg * 2;
            #pragma unroll
            for (int half = 0; half < 2; half++) {
                int r = rbase + m * 16 + g + half * 8;
                float v0 = d1[m][j][half * 2 + 0];
                float v1 = d1[m][j][half * 2 + 1];
                if (DUAL) {
                    float w0 = d3[m][j][half * 2 + 0];
                    float w1 = d3[m][j][half * 2 + 1];
                    v0 = (v0 / (1.f + __expf(-v0))) * w0;
                    v1 = (v1 / (1.f + __expf(-v1))) * w1;
                }
                if (MODE == 0) {
                    if (r < M && col < N) {
                        size_t o = (size_t)r * N + col;
                        if (bias) { v0 += bias[col]; v1 += bias[col + 1]; }
                        if (accum) { C[o] += v0; C[o + 1] += v1; }
                        else       { C[o] = v0;  C[o + 1] = v1; }
                    }
                } else if (MODE == 1) {
                    size_t o = (size_t)r * N + col;
                    C[o] = v0; C[o + 1] = v1;
                } else if (MODE == 2) {
                    if (r < cnt) {
                        size_t o = (size_t)r * Ic + col;
                        Cp[o] = v0; Cp[o + 1] = v1;
                    }
                } else {  // MODE 3
                    if (r < cnt) {
                        int tok2 = g_list[e * Tc + r];
                        float wgt = g_topw[tok2];
                        size_t o = (size_t)tok2 * Hc + col;
                        C[o] = v0 * wgt; C[o + 1] = v1 * wgt;
                    }
                }
            }
        }
    }
}

// ---------------- RMSNorm ----------------
__global__ void rms_kernel(const float* __restrict__ in, int instride,
                           const float* __restrict__ w,
                           float* __restrict__ out, int outstride, int n)
{
    int t = blockIdx.x, tid = threadIdx.x;
    const float* row = in + (size_t)t * instride;
    __shared__ float sred[256];
    float ss = 0.f;
    for (int j = tid; j < n; j += 256) { float v = row[j]; ss += v * v; }
    sred[tid] = ss; __syncthreads();
    for (int o = 128; o; o >>= 1) { if (tid < o) sred[tid] += sred[tid + o]; __syncthreads(); }
    float inv = rsqrtf(sred[0] / n + 1e-6f);
    float* orow = out + (size_t)t * outstride;
    for (int j = tid; j < n; j += 256) orow[j] = row[j] * inv * w[j];
}

// ---------------- RoPE ----------------
__global__ void rope_kernel()
{
    int t = blockIdx.x;
    int pos = t % Sc;
    int tid = threadIdx.x;
    int vec = tid >> 4, i = tid & 15;
    if (vec >= NHc + 1) return;
    float* base = (vec < NHc) ? &g_q[(size_t)t * (NHc * QD) + vec * QD + DNc]
                              : &g_kva[(size_t)t * KVAW + Rc];
    int j1 = i, j2 = i + 16;
    float f1 = powf(10000.0f, -(float)(2 * j1) / 64.0f);
    float f2 = powf(10000.0f, -(float)(2 * j2) / 64.0f);
    float s1, c1, s2, c2;
    sincosf(pos * f1, &s1, &c1);
    sincosf(pos * f2, &s2, &c2);
    float x1 = base[j1], x2 = base[j2];
    base[j1] = x1 * c1 - x2 * s1;
    base[j2] = x2 * c2 + x1 * s2;
}

// ---------------- flash attention ----------------
#define ALD 68
__global__ __launch_bounds__(256) void attn_kernel()
{
    int qt  = (int)gridDim.x - 1 - (int)blockIdx.x;
    int hId = blockIdx.y, b = blockIdx.z;
    int tid = threadIdx.x;
    int tx = tid & 15, ty = tid >> 4;
    int lr = tid >> 2, sub = tid & 3;

    extern __shared__ float sm[];
    float* qsT = sm;
    float* ksT = sm + 64 * ALD;
    float* vs  = sm + 2 * 64 * ALD;
    float* ps  = sm + 3 * 64 * ALD;

    int q0 = qt * 64;
    {
        const float* qrow = &g_q[(size_t)(b * Sc + q0 + lr) * (NHc * QD) + hId * QD];
        #pragma unroll
        for (int i = 0; i < 16; i++) {
            int d = sub * 16 + i;
            qsT[d * ALD + lr] = qrow[d];
        }
    }

    float m[4], l[4], acc[4][4];
    #pragma unroll
    for (int i = 0; i < 4; i++) {
        m[i] = -1e30f; l[i] = 0.f;
        #pragma unroll
        for (int j = 0; j < 4; j++) acc[i][j] = 0.f;
    }

    for (int kt = 0; kt <= qt; kt++) {
        __syncthreads();
        {
            int kg = b * Sc + kt * 64 + lr;
            const float* kn = &g_kv [(size_t)kg * (NHc * KVD) + hId * KVD];
            const float* kp = &g_kva[(size_t)kg * KVAW + Rc];
            #pragma unroll
            for (int i = 0; i < 8; i++) {
                int d = sub * 8 + i;
                ksT[d * ALD + lr]        = kn[d];
                ksT[(32 + d) * ALD + lr] = kp[d];
            }
            const float* vp = kn + DNc;
            #pragma unroll
            for (int i = 0; i < 4; i++)
                *(float4*)&vs[lr * ALD + sub * 16 + i * 4] = *(const float4*)(vp + sub * 16 + i * 4);
        }
        __syncthreads();

        float s[4][4] = {};
        #pragma unroll
        for (int d = 0; d < 64; d++) {
            float4 a4 = *(const float4*)&qsT[d * ALD + ty * 4];
            float4 b4 = *(const float4*)&ksT[d * ALD + tx * 4];
            float av[4] = {a4.x, a4.y, a4.z, a4.w};
            float bv[4] = {b4.x, b4.y, b4.z, b4.w};
            #pragma unroll
            for (int i = 0; i < 4; i++)
                #pragma unroll
                for (int j = 0; j < 4; j++)
                    s[i][j] += av[i] * bv[j];
        }
        #pragma unroll
        for (int i = 0; i < 4; i++)
            #pragma unroll
            for (int j = 0; j < 4; j++) {
                float v = s[i][j] * 0.125f;
                if (kt == qt && (tx * 4 + j) > (ty * 4 + i)) v = -1e30f;
                s[i][j] = v;
            }

        #pragma unroll
        for (int i = 0; i < 4; i++) {
            float mx = fmaxf(fmaxf(s[i][0], s[i][1]), fmaxf(s[i][2], s[i][3]));
            #pragma unroll
            for (int o = 1; o < 16; o <<= 1) mx = fmaxf(mx, __shfl_xor_sync(0xffffffffu, mx, o));
            float mn = fmaxf(m[i], mx);
            float alpha = __expf(m[i] - mn);
            float sum = 0.f;
            #pragma unroll
            for (int j = 0; j < 4; j++) { float p = __expf(s[i][j] - mn); s[i][j] = p; sum += p; }
            #pragma unroll
            for (int o = 1; o < 16; o <<= 1) sum += __shfl_xor_sync(0xffffffffu, sum, o);
            l[i] = l[i] * alpha + sum;
            m[i] = mn;
            #pragma unroll
            for (int j = 0; j < 4; j++) acc[i][j] *= alpha;
            #pragma unroll
            for (int j = 0; j < 4; j++) ps[(ty * 4 + i) * ALD + tx * 4 + j] = s[i][j];
        }
        __syncthreads();

        #pragma unroll 8
        for (int j = 0; j < 64; j++) {
            float4 b4 = *(const float4*)&vs[j * ALD + tx * 4];
            float bv[4] = {b4.x, b4.y, b4.z, b4.w};
            #pragma unroll
            for (int i = 0; i < 4; i++) {
                float a = ps[(ty * 4 + i) * ALD + j];
                #pragma unroll
                for (int jj = 0; jj < 4; jj++) acc[i][jj] += a * bv[jj];
            }
        }
    }

    #pragma unroll
    for (int i = 0; i < 4; i++) {
        float inv = 1.f / l[i];
        int t = b * Sc + q0 + ty * 4 + i;
        #pragma unroll
        for (int jj = 0; jj < 4; jj++)
            g_attn[(size_t)t * Hc + hId * DVc + tx * 4 + jj] = acc[i][jj] * inv;
    }
}

// ---------------- gating ----------------
__global__ void zero_cnt_kernel() { if (threadIdx.x < Ec) g_cnt[threadIdx.x] = 0; }

__global__ void gate_kernel(const float* __restrict__ gw)
{
    int t = blockIdx.x, tid = threadIdx.x;
    int w = tid >> 5, lane = tid & 31;
    const float* xrow = &g_x[(size_t)t * Hc];
    const float* grow = gw + (size_t)w * Hc;
    float s = 0.f;
    for (int k = lane; k < Hc; k += 32) s += xrow[k] * grow[k];
    s = warpsum(s);
    __shared__ float logit[Ec];
    if (lane == 0) logit[w] = s;
    __syncthreads();
    if (tid == 0) {
        float mx = -1e30f;
        for (int e = 0; e < Ec; e++) mx = fmaxf(mx, logit[e]);
        float ex[Ec];
        for (int e = 0; e < Ec; e++) ex[e] = expf(logit[e] - mx);
        int i0 = 0;
        for (int e = 1; e < Ec; e++) if (ex[e] > ex[i0]) i0 = e;
        int i1 = (i0 == 0) ? 1 : 0;
        for (int e = 0; e < Ec; e++) if (e != i0 && ex[e] > ex[i1]) i1 = e;
        float p0 = ex[i0], p1 = ex[i1], tsum = p0 + p1;
        g_topw[t * 2]     = p0 / tsum;
        g_topw[t * 2 + 1] = p1 / tsum;
        int pos0 = atomicAdd(&g_cnt[i0], 1);
        g_list[i0 * Tc + pos0] = t * 2;
        int pos1 = atomicAdd(&g_cnt[i1], 1);
        g_list[i1 * Tc + pos1] = t * 2 + 1;
    }
}

__global__ void combine_kernel()
{
    int i = blockIdx.x * 256 + threadIdx.x;
    int t = i / Hc, j = i - t * Hc;
    g_h[i] += g_eo[(size_t)(t * 2) * Hc + j] + g_eo[(size_t)(t * 2 + 1) * Hc + j];
}

__global__ void final_kernel(const float* __restrict__ fw, const float* __restrict__ hw,
                             const float* __restrict__ hb, float* __restrict__ out)
{
    int b = blockIdx.x, tid = threadIdx.x;
    int t = b * Sc + (Sc - 1);
    const float* row = &g_h[(size_t)t * Hc];
    __shared__ float sred[256];
    float ss = 0.f;
    for (int j = tid; j < Hc; j += 256) { float v = row[j]; ss += v * v; }
    sred[tid] = ss; __syncthreads();
    for (int o = 128; o; o >>= 1) { if (tid < o) sred[tid] += sred[tid + o]; __syncthreads(); }
    float inv = rsqrtf(sred[0] / Hc + 1e-6f);
    __syncthreads();
    float acc = 0.f;
    for (int j = tid; j < Hc; j += 256) acc += row[j] * inv * fw[j] * hw[j];
    sred[tid] = acc; __syncthreads();
    for (int o = 128; o; o >>= 1) { if (tid < o) sred[tid] += sred[tid + o]; __syncthreads(); }
    if (tid == 0) out[b] = sred[0] + hb[0];
}

// ---------------- host launch ----------------
#define SMEM_SINGLE ((4 * ASZ_W + 4 * 64  * LDW) * 4)   // 73728 B
#define SMEM_DUAL   ((4 * ASZ_W + 4 * 128 * LDW) * 4)   // 110592 B

static inline void tc_dense(const float* A, const float* Bw, const float* bias, float* C,
                            int M, int N, int Kd, int accum)
{
    dim3 grid((N + 63) / 64, M / 64, 1);
    mma_gemm_kernel<0><<<grid, 128, SMEM_SINGLE>>>(A, Bw, nullptr, bias, C, M, N, Kd, accum);
}

extern "C" void kernel_launch(void* const* d_in, const int* in_sizes, int n_in,
                              void* d_out, int out_size)
{
    const float* inputs   = (const float*)d_in[0];
    const float* in_w     = (const float*)d_in[1];
    const float* in_b     = (const float*)d_in[2];
    const float* attn_nw  = (const float*)d_in[3];
    const float* wq       = (const float*)d_in[4];
    const float* wkva     = (const float*)d_in[5];
    const float* kvn_w    = (const float*)d_in[6];
    const float* wkvb     = (const float*)d_in[7];
    const float* wo       = (const float*)d_in[8];
    const float* moe_nw   = (const float*)d_in[9];
    const float* gate_w   = (const float*)d_in[10];
    const float* e_w1     = (const float*)d_in[11];
    const float* e_w2     = (const float*)d_in[12];
    const float* e_w3     = (const float*)d_in[13];
    const float* s_w1     = (const float*)d_in[14];
    const float* s_w2     = (const float*)d_in[15];
    const float* s_w3     = (const float*)d_in[16];
    const float* final_nw = (const float*)d_in[17];
    const float* head_w   = (const float*)d_in[18];
    const float* head_b   = (const float*)d_in[19];
    float* out = (float*)d_out;

    float *h_p, *x_p, *q_p, *kva_p, *ckv_p, *kv_p, *attn_p, *t1_p, *mg_p, *eo_p;
    cudaGetSymbolAddress((void**)&h_p,    g_h);
    cudaGetSymbolAddress((void**)&x_p,    g_x);
    cudaGetSymbolAddress((void**)&q_p,    g_q);
    cudaGetSymbolAddress((void**)&kva_p,  g_kva);
    cudaGetSymbolAddress((void**)&ckv_p,  g_ckv);
    cudaGetSymbolAddress((void**)&kv_p,   g_kv);
    cudaGetSymbolAddress((void**)&attn_p, g_attn);
    cudaGetSymbolAddress((void**)&t1_p,   g_t1);
    cudaGetSymbolAddress((void**)&mg_p,   g_mg);
    cudaGetSymbolAddress((void**)&eo_p,   g_eo);

    cudaFuncSetAttribute(mma_gemm_kernel<0>, cudaFuncAttributeMaxDynamicSharedMemorySize, SMEM_SINGLE);
    cudaFuncSetAttribute(mma_gemm_kernel<1>, cudaFuncAttributeMaxDynamicSharedMemorySize, SMEM_DUAL);
    cudaFuncSetAttribute(mma_gemm_kernel<2>, cudaFuncAttributeMaxDynamicSharedMemorySize, SMEM_DUAL);
    cudaFuncSetAttribute(mma_gemm_kernel<3>, cudaFuncAttributeMaxDynamicSharedMemorySize, SMEM_SINGLE);

    const int attn_smem = 4 * 64 * ALD * sizeof(float);
    cudaFuncSetAttribute(attn_kernel, cudaFuncAttributeMaxDynamicSharedMemorySize, attn_smem);

    // embed: h = inputs @ in_w^T + in_b   (K=64)
    tc_dense(inputs, in_w, in_b, h_p, Tc, Hc, 64, 0);

    for (int l = 0; l < Lc; l++) {
        const float* anw   = attn_nw + (size_t)l * Hc;
        const float* wq_l  = wq      + (size_t)l * Hc * Hc;
        const float* wva_l = wkva    + (size_t)l * KVAW * Hc;
        const float* kvn_l = kvn_w   + (size_t)l * Rc;
        const float* wvb_l = wkvb    + (size_t)l * (NHc * KVD) * Rc;
        const float* wo_l  = wo      + (size_t)l * Hc * Hc;
        const float* mnw   = moe_nw  + (size_t)l * Hc;
        const float* gw_l  = gate_w  + (size_t)l * Ec * Hc;
        const float* w1_l  = e_w1    + (size_t)l * Ec * Ic * Hc;
        const float* w2_l  = e_w2    + (size_t)l * Ec * Hc * Ic;
        const float* w3_l  = e_w3    + (size_t)l * Ec * Ic * Hc;
        const float* sw1_l = s_w1    + (size_t)l * SIc * Hc;
        const float* sw2_l = s_w2    + (size_t)l * Hc * SIc;
        const float* sw3_l = s_w3    + (size_t)l * SIc * Hc;

        // attention
        rms_kernel<<<Tc, 256>>>(h_p, Hc, anw, x_p, Hc, Hc);
        tc_dense(x_p, wq_l,  nullptr, q_p,   Tc, Hc,   Hc, 0);
        tc_dense(x_p, wva_l, nullptr, kva_p, Tc, KVAW, Hc, 0);
        rope_kernel<<<Tc, 256>>>();
        rms_kernel<<<Tc, 256>>>(kva_p, KVAW, kvn_l, ckv_p, Rc, Rc);
        tc_dense(ckv_p, wvb_l, nullptr, kv_p, Tc, NHc * KVD, Rc, 0);
        {
            dim3 grid(Sc / 64, NHc, Bc);
            attn_kernel<<<grid, 256, attn_smem>>>();
        }
        tc_dense(attn_p, wo_l, nullptr, h_p, Tc, Hc, Hc, 1);

        // MoE
        rms_kernel<<<Tc, 256>>>(h_p, Hc, mnw, x_p, Hc, Hc);
        zero_cnt_kernel<<<1, 32>>>();
        gate_kernel<<<Tc, 256>>>(gw_l);
        {
            dim3 g1(Ic / 64, Tc / 64, Ec);
            mma_gemm_kernel<2><<<g1, 128, SMEM_DUAL>>>(x_p, w1_l, w3_l, nullptr, mg_p, Tc, Ic, Hc, 0);
            dim3 g2(Hc / 64, Tc / 64, Ec);
            mma_gemm_kernel<3><<<g2, 128, SMEM_SINGLE>>>(mg_p, w2_l, nullptr, nullptr, eo_p, Tc, Hc, Ic, 0);
            combine_kernel<<<(Tc * Hc) / 256, 256>>>();
        }
        // shared FFN: t1 = silu(x@sw1^T)*(x@sw3^T); h += t1 @ sw2^T
        {
            dim3 gd(SIc / 64, Tc / 64, 1);
            mma_gemm_kernel<1><<<gd, 128, SMEM_DUAL>>>(x_p, sw1_l, sw3_l, nullptr, t1_p, Tc, SIc, Hc, 0);
        }
        tc_dense(t1_p, sw2_l, nullptr, h_p, Tc, Hc, SIc, 1);
    }

    final_kernel<<<Bc, 256>>>(final_nw, head_w, head_b, out);
}

// round 11
// speedup vs baseline: 1.0679x; 1.0679x over previous
#include <cuda_runtime.h>
#include <math.h>
#include <stdint.h>

// ---------------- model constants ----------------
#define Lc   12
#define Hc   768
#define NHc  12
#define DNc  32
#define DRc  32
#define DVc  64
#define Rc   512
#define Ec   8
#define KTOP 2
#define Ic   256
#define SIc  1024
#define Bc   2
#define Sc   512
#define Tc   (Bc*Sc)
#define QD   (DNc+DRc)        // 64
#define KVD  (DNc+DVc)        // 96
#define KVAW (Rc+DRc)         // 544

// ---------------- scratch (device globals, no allocation) ----------------
__device__ float g_h   [Tc*Hc];
__device__ float g_x   [Tc*Hc];
__device__ float g_q   [Tc*(NHc*QD)];
__device__ float g_kva [Tc*KVAW];
__device__ float g_ckv [Tc*Rc];
__device__ float g_kv  [Tc*(NHc*KVD)];
__device__ float g_attn[Tc*Hc];
__device__ float g_t1  [Tc*SIc];
__device__ float g_mg  [Ec*Tc*Ic];
__device__ float g_eo  [Tc*2*Hc];
__device__ int   g_list[Ec*Tc];
__device__ int   g_cnt [Ec];
__device__ float g_topw[Tc*KTOP];

// ---------------- helpers ----------------
__device__ __forceinline__ float warpsum(float v) {
    #pragma unroll
    for (int o = 16; o; o >>= 1) v += __shfl_down_sync(0xffffffffu, v, o);
    return v;
}

__device__ __forceinline__ uint32_t f2tf(float x) {
    uint32_t u;
    asm("cvt.rna.tf32.f32 %0, %1;" : "=r"(u) : "f"(x));
    return u;
}
__device__ __forceinline__ void tfsplit(float x, uint32_t& hi, uint32_t& lo) {
    hi = f2tf(x);
    lo = f2tf(x - __uint_as_float(hi));
}
__device__ __forceinline__ void split4(float4 v, float4& hi, float4& lo) {
    hi.x = __uint_as_float(f2tf(v.x)); lo.x = __uint_as_float(f2tf(v.x - hi.x));
    hi.y = __uint_as_float(f2tf(v.y)); lo.y = __uint_as_float(f2tf(v.y - hi.y));
    hi.z = __uint_as_float(f2tf(v.z)); lo.z = __uint_as_float(f2tf(v.z - hi.z));
    hi.w = __uint_as_float(f2tf(v.w)); lo.w = __uint_as_float(f2tf(v.w - hi.w));
}

__device__ __forceinline__ uint32_t smem_u32(const void* p) {
    uint32_t a;
    asm("{ .reg .u64 t; cvta.to.shared.u64 t, %1; cvt.u32.u64 %0, t; }" : "=r"(a) : "l"(p));
    return a;
}

#define MMA_TF32(d, a0, a1, a2, a3, b0, b1) \
    asm volatile("mma.sync.aligned.m16n8k8.row.col.f32.tf32.tf32.f32 " \
        "{%0,%1,%2,%3}, {%4,%5,%6,%7}, {%8,%9}, {%0,%1,%2,%3};" \
        : "+f"((d)[0]), "+f"((d)[1]), "+f"((d)[2]), "+f"((d)[3]) \
        : "r"(a0), "r"(a1), "r"(a2), "r"(a3), "r"(b0), "r"(b1))

#define CP_ASYNC16(dst, src, sz) \
    asm volatile("cp.async.cg.shared.global [%0], [%1], 16, %2;" \
        :: "r"(dst), "l"(src), "r"(sz) : "memory")
#define CP_COMMIT asm volatile("cp.async.commit_group;" ::: "memory")
#define CP_WAIT(n) asm volatile("cp.async.wait_group %0;" :: "n"(n) : "memory")

// ---------------- tensor-core 3xtf32 GEMM (64x64 CTA tile, 128 thr) — R6 best ------
#define LDW  36
#define ASZ_W (64*LDW)

template<int MODE>
__global__ __launch_bounds__(128) void mma_gemm_kernel(
    const float* __restrict__ A, const float* __restrict__ B1w,
    const float* __restrict__ B3w, const float* __restrict__ bias,
    float* __restrict__ C, int M, int N, int Kd, int accum)
{
    constexpr bool DUAL  = (MODE == 1 || MODE == 2);
    constexpr int  BROWS = DUAL ? 128 : 64;
    constexpr int  BSZ_W = BROWS * LDW;

    int tid = threadIdx.x;
    int wid = tid >> 5, lane = tid & 31;
    int g = lane >> 2, tg = lane & 3;
    int warpM = wid & 1, warpN = wid >> 1;

    int e   = (MODE >= 2) ? blockIdx.z : 0;
    int cnt = (MODE >= 2) ? g_cnt[e] : M;
    int row0 = blockIdx.y * 64;
    if (row0 >= cnt) return;
    int col0 = blockIdx.x * 64;

    const float* Ap  = A;
    const float* B1p = B1w;
    const float* B3p = B3w;
    float* Cp = C;
    if (MODE == 2) {
        B1p = B1w + (size_t)e * Ic * Hc;
        B3p = B3w + (size_t)e * Ic * Hc;
        Cp  = C + (size_t)e * Tc * Ic;
    }
    if (MODE == 3) {
        Ap  = A + (size_t)e * Tc * Ic;
        B1p = B1w + (size_t)e * Hc * Ic;
    }

    extern __shared__ float dsm[];
    __shared__ int s_tok[64];

    if (MODE == 2) {
        if (tid < 64) {
            int grow = row0 + tid;
            int tok2 = (grow < cnt) ? g_list[e * Tc + grow] : 0;
            s_tok[tid] = tok2 >> 1;
        }
        __syncthreads();
    }

    uint32_t sbase = smem_u32(dsm);
    int lc4 = tid & 7;
    int lrb = tid >> 3;

    int nchunks = Kd / 32;

    auto issue_chunk = [&](int ch, int buf) {
        int c0 = ch * 32 + lc4 * 4;
        uint32_t sA = sbase + (uint32_t)(buf * ASZ_W) * 4u;
        uint32_t sB = sbase + (uint32_t)(2 * ASZ_W + buf * BSZ_W) * 4u;
        #pragma unroll
        for (int i = 0; i < 4; i++) {
            int r = lrb + i * 16;
            const float* src = (MODE == 2) ? &g_x[(size_t)s_tok[r] * Hc + c0]
                                           : Ap + (size_t)(row0 + r) * Kd + c0;
            CP_ASYNC16(sA + (uint32_t)(r * LDW + lc4 * 4) * 4u, src, 16);
        }
        #pragma unroll
        for (int i = 0; i < (DUAL ? 8 : 4); i++) {
            int r = lrb + i * 16;
            int gn; const float* base;
            if (!DUAL) { gn = col0 + r; base = B1p; }
            else if (r < 64) { gn = col0 + r; base = B1p; }
            else { gn = col0 + r - 64; base = B3p; }
            int ok = (gn < N) ? 16 : 0;
            const float* src = base + (size_t)(ok ? gn : 0) * Kd + c0;
            CP_ASYNC16(sB + (uint32_t)(r * LDW + lc4 * 4) * 4u, src, ok);
        }
        CP_COMMIT;
    };

    issue_chunk(0, 0);
    if (nchunks > 1) issue_chunk(1, 1);

    float d1[2][4][4];
    float d3[DUAL ? 2 : 1][DUAL ? 4 : 1][4];
    #pragma unroll
    for (int m = 0; m < 2; m++)
        #pragma unroll
        for (int j = 0; j < 4; j++)
            #pragma unroll
            for (int q = 0; q < 4; q++) {
                d1[m][j][q] = 0.f;
                if (DUAL) d3[m][j][q] = 0.f;
            }

    for (int c = 0; c < nchunks; c++) {
        if (c + 2 <= nchunks) { CP_WAIT(1); } else { CP_WAIT(0); }
        __syncthreads();

        const float* Ab  = dsm + (c & 1) * ASZ_W + (warpM * 32) * LDW;
        const float* Bb  = dsm + 2 * ASZ_W + (c & 1) * BSZ_W + (warpN * 32) * LDW;
        const float* Bb3 = Bb + 64 * LDW;

        #pragma unroll
        for (int ks = 0; ks < 4; ks++) {
            int kc = ks * 8 + tg;
            uint32_t ahi[2][4], alo[2][4];
            #pragma unroll
            for (int m = 0; m < 2; m++) {
                const float* ap = Ab + (m * 16 + g) * LDW;
                tfsplit(ap[kc],               ahi[m][0], alo[m][0]);
                tfsplit(ap[8 * LDW + kc],     ahi[m][1], alo[m][1]);
                tfsplit(ap[kc + 4],           ahi[m][2], alo[m][2]);
                tfsplit(ap[8 * LDW + kc + 4], ahi[m][3], alo[m][3]);
            }
            #pragma unroll
            for (int j = 0; j < 4; j++) {
                const float* bp = Bb + (j * 8 + g) * LDW;
                uint32_t bh0, bl0, bh1, bl1;
                tfsplit(bp[kc],     bh0, bl0);
                tfsplit(bp[kc + 4], bh1, bl1);
                #pragma unroll
                for (int m = 0; m < 2; m++) {
                    MMA_TF32(d1[m][j], ahi[m][0], ahi[m][1], ahi[m][2], ahi[m][3], bh0, bh1);
                    MMA_TF32(d1[m][j], alo[m][0], alo[m][1], alo[m][2], alo[m][3], bh0, bh1);
                    MMA_TF32(d1[m][j], ahi[m][0], ahi[m][1], ahi[m][2], ahi[m][3], bl0, bl1);
                }
            }
            if (DUAL) {
                #pragma unroll
                for (int j = 0; j < 4; j++) {
                    const float* bp = Bb3 + (j * 8 + g) * LDW;
                    uint32_t bh0, bl0, bh1, bl1;
                    tfsplit(bp[kc],     bh0, bl0);
                    tfsplit(bp[kc + 4], bh1, bl1);
                    #pragma unroll
                    for (int m = 0; m < 2; m++) {
                        MMA_TF32(d3[m][j], ahi[m][0], ahi[m][1], ahi[m][2], ahi[m][3], bh0, bh1);
                        MMA_TF32(d3[m][j], alo[m][0], alo[m][1], alo[m][2], alo[m][3], bh0, bh1);
                        MMA_TF32(d3[m][j], ahi[m][0], ahi[m][1], ahi[m][2], ahi[m][3], bl0, bl1);
                    }
                }
            }
        }
        __syncthreads();
        if (c + 2 < nchunks) issue_chunk(c + 2, c & 1);
    }

    int rbase = row0 + warpM * 32;
    int cbase = col0 + warpN * 32;

    #pragma unroll
    for (int m = 0; m < 2; m++) {
        #pragma unroll
        for (int j = 0; j < 4; j++) {
            int col = cbase + j * 8 + tg * 2;
            #pragma unroll
            for (int half = 0; half < 2; half++) {
                int r = rbase + m * 16 + g + half * 8;
                float v0 = d1[m][j][half * 2 + 0];
                float v1 = d1[m][j][half * 2 + 1];
                if (DUAL) {
                    float w0 = d3[m][j][half * 2 + 0];
                    float w1 = d3[m][j][half * 2 + 1];
                    v0 = (v0 / (1.f + __expf(-v0))) * w0;
                    v1 = (v1 / (1.f + __expf(-v1))) * w1;
                }
                if (MODE == 0) {
                    if (r < M && col < N) {
                        size_t o = (size_t)r * N + col;
                        if (bias) { v0 += bias[col]; v1 += bias[col + 1]; }
                        if (accum) { C[o] += v0; C[o + 1] += v1; }
                        else       { C[o] = v0;  C[o + 1] = v1; }
                    }
                } else if (MODE == 1) {
                    size_t o = (size_t)r * N + col;
                    C[o] = v0; C[o + 1] = v1;
                } else if (MODE == 2) {
                    if (r < cnt) {
                        size_t o = (size_t)r * Ic + col;
                        Cp[o] = v0; Cp[o + 1] = v1;
                    }
                } else {
                    if (r < cnt) {
                        int tok2 = g_list[e * Tc + r];
                        float wgt = g_topw[tok2];
                        size_t o = (size_t)tok2 * Hc + col;
                        C[o] = v0 * wgt; C[o + 1] = v1 * wgt;
                    }
                }
            }
        }
    }
}

// ---------------- RMSNorm ----------------
__global__ void rms_kernel(const float* __restrict__ in, int instride,
                           const float* __restrict__ w,
                           float* __restrict__ out, int outstride, int n)
{
    int t = blockIdx.x, tid = threadIdx.x;
    const float* row = in + (size_t)t * instride;
    __shared__ float sred[256];
    float ss = 0.f;
    for (int j = tid; j < n; j += 256) { float v = row[j]; ss += v * v; }
    sred[tid] = ss; __syncthreads();
    for (int o = 128; o; o >>= 1) { if (tid < o) sred[tid] += sred[tid + o]; __syncthreads(); }
    float inv = rsqrtf(sred[0] / n + 1e-6f);
    float* orow = out + (size_t)t * outstride;
    for (int j = tid; j < n; j += 256) orow[j] = row[j] * inv * w[j];
}

// ---------------- RoPE ----------------
__global__ void rope_kernel()
{
    int t = blockIdx.x;
    int pos = t % Sc;
    int tid = threadIdx.x;
    int vec = tid >> 4, i = tid & 15;
    if (vec >= NHc + 1) return;
    float* base = (vec < NHc) ? &g_q[(size_t)t * (NHc * QD) + vec * QD + DNc]
                              : &g_kva[(size_t)t * KVAW + Rc];
    int j1 = i, j2 = i + 16;
    float f1 = powf(10000.0f, -(float)(2 * j1) / 64.0f);
    float f2 = powf(10000.0f, -(float)(2 * j2) / 64.0f);
    float s1, c1, s2, c2;
    sincosf(pos * f1, &s1, &c1);
    sincosf(pos * f2, &s2, &c2);
    float x1 = base[j1], x2 = base[j2];
    base[j1] = x1 * c1 - x2 * s1;
    base[j2] = x2 * c2 + x1 * s2;
}

// ---------------- flash attention on tensor cores (3xtf32) ----------------
// Block per (qtile 64, head, batch), 128 thr / 4 warps; warp tile 16 q-rows x 64.
#define SLD 68
#define ATTN_SMEM (8 * 64 * SLD * 4)

__global__ __launch_bounds__(128) void attn_kernel()
{
    int qt  = (int)gridDim.x - 1 - (int)blockIdx.x;
    int hId = blockIdx.y, b = blockIdx.z;
    int tid = threadIdx.x;
    int wid = tid >> 5, lane = tid & 31;
    int g = lane >> 2, tg = lane & 3;
    int lr = tid >> 1, half = tid & 1;

    extern __shared__ float sm[];
    float* QH = sm;
    float* QL = sm + 1 * 64 * SLD;
    float* KH = sm + 2 * 64 * SLD;
    float* KL = sm + 3 * 64 * SLD;
    float* VH = sm + 4 * 64 * SLD;
    float* VL = sm + 5 * 64 * SLD;
    float* PH = sm + 6 * 64 * SLD;
    float* PL = sm + 7 * 64 * SLD;

    int q0 = qt * 64;

    // load Q tile (rows q-local, cols d), split once
    {
        const float* qrow = &g_q[(size_t)(b * Sc + q0 + lr) * (NHc * QD) + hId * QD + half * 32];
        #pragma unroll
        for (int i = 0; i < 8; i++) {
            float4 v = *(const float4*)(qrow + i * 4);
            float4 hi, lo; split4(v, hi, lo);
            int c = half * 32 + i * 4;
            *(float4*)&QH[lr * SLD + c] = hi;
            *(float4*)&QL[lr * SLD + c] = lo;
        }
    }

    float mrow[2] = { -1e30f, -1e30f };
    float lsum[2] = { 0.f, 0.f };
    float acc[8][4];
    #pragma unroll
    for (int j = 0; j < 8; j++)
        #pragma unroll
        for (int q = 0; q < 4; q++) acc[j][q] = 0.f;

    int prow = wid * 16 + g;   // local q row (first of pair)

    for (int kt = 0; kt <= qt; kt++) {
        __syncthreads();
        // load K tile rows [key][d] and V transposed [dv][key], split
        {
            int kg = b * Sc + kt * 64 + lr;
            const float* src = (half == 0) ? &g_kv [(size_t)kg * (NHc * KVD) + hId * KVD]
                                           : &g_kva[(size_t)kg * KVAW + Rc];
            #pragma unroll
            for (int i = 0; i < 8; i++) {
                float4 v = *(const float4*)(src + i * 4);
                float4 hi, lo; split4(v, hi, lo);
                int c = half * 32 + i * 4;
                *(float4*)&KH[lr * SLD + c] = hi;
                *(float4*)&KL[lr * SLD + c] = lo;
            }
            const float* vp = &g_kv[(size_t)kg * (NHc * KVD) + hId * KVD + DNc + half * 32];
            #pragma unroll
            for (int i = 0; i < 8; i++) {
                float4 v = *(const float4*)(vp + i * 4);
                float4 hi, lo; split4(v, hi, lo);
                int dv = half * 32 + i * 4;
                VH[(dv + 0) * SLD + lr] = hi.x; VL[(dv + 0) * SLD + lr] = lo.x;
                VH[(dv + 1) * SLD + lr] = hi.y; VL[(dv + 1) * SLD + lr] = lo.y;
                VH[(dv + 2) * SLD + lr] = hi.z; VL[(dv + 2) * SLD + lr] = lo.z;
                VH[(dv + 3) * SLD + lr] = hi.w; VL[(dv + 3) * SLD + lr] = lo.w;
            }
        }
        __syncthreads();

        // ---- S = Q @ K^T (3xtf32) ----
        float sf[8][4];
        #pragma unroll
        for (int j = 0; j < 8; j++)
            #pragma unroll
            for (int q = 0; q < 4; q++) sf[j][q] = 0.f;

        #pragma unroll
        for (int ks = 0; ks < 8; ks++) {
            int kc = ks * 8 + tg;
            const float* qh = QH + prow * SLD;
            const float* ql = QL + prow * SLD;
            uint32_t ah0 = __float_as_uint(qh[kc]);
            uint32_t ah1 = __float_as_uint(qh[8 * SLD + kc]);
            uint32_t ah2 = __float_as_uint(qh[kc + 4]);
            uint32_t ah3 = __float_as_uint(qh[8 * SLD + kc + 4]);
            uint32_t al0 = __float_as_uint(ql[kc]);
            uint32_t al1 = __float_as_uint(ql[8 * SLD + kc]);
            uint32_t al2 = __float_as_uint(ql[kc + 4]);
            uint32_t al3 = __float_as_uint(ql[8 * SLD + kc + 4]);
            #pragma unroll
            for (int j = 0; j < 8; j++) {
                const float* kh = KH + (j * 8 + g) * SLD;
                const float* kl = KL + (j * 8 + g) * SLD;
                uint32_t bh0 = __float_as_uint(kh[kc]);
                uint32_t bh1 = __float_as_uint(kh[kc + 4]);
                uint32_t bl0 = __float_as_uint(kl[kc]);
                uint32_t bl1 = __float_as_uint(kl[kc + 4]);
                MMA_TF32(sf[j], ah0, ah1, ah2, ah3, bh0, bh1);
                MMA_TF32(sf[j], al0, al1, al2, al3, bh0, bh1);
                MMA_TF32(sf[j], ah0, ah1, ah2, ah3, bl0, bl1);
            }
        }

        // ---- scale + causal mask ----
        int qrow0 = q0 + prow, qrow1 = qrow0 + 8;
        #pragma unroll
        for (int j = 0; j < 8; j++) {
            int k0 = kt * 64 + j * 8 + tg * 2;
            sf[j][0] = (k0     <= qrow0) ? sf[j][0] * 0.125f : -1e30f;
            sf[j][1] = (k0 + 1 <= qrow0) ? sf[j][1] * 0.125f : -1e30f;
            sf[j][2] = (k0     <= qrow1) ? sf[j][2] * 0.125f : -1e30f;
            sf[j][3] = (k0 + 1 <= qrow1) ? sf[j][3] * 0.125f : -1e30f;
        }

        // ---- online softmax (rows warp-local; reduce over tg lanes) ----
        float mx0 = -1e30f, mx1 = -1e30f;
        #pragma unroll
        for (int j = 0; j < 8; j++) {
            mx0 = fmaxf(mx0, fmaxf(sf[j][0], sf[j][1]));
            mx1 = fmaxf(mx1, fmaxf(sf[j][2], sf[j][3]));
        }
        #pragma unroll
        for (int o = 1; o < 4; o <<= 1) {
            mx0 = fmaxf(mx0, __shfl_xor_sync(0xffffffffu, mx0, o));
            mx1 = fmaxf(mx1, __shfl_xor_sync(0xffffffffu, mx1, o));
        }
        float mn0 = fmaxf(mrow[0], mx0), mn1 = fmaxf(mrow[1], mx1);
        float alpha0 = __expf(mrow[0] - mn0), alpha1 = __expf(mrow[1] - mn1);
        mrow[0] = mn0; mrow[1] = mn1;

        float s0 = 0.f, s1 = 0.f;
        #pragma unroll
        for (int j = 0; j < 8; j++) {
            float p0 = __expf(sf[j][0] - mn0);
            float p1 = __expf(sf[j][1] - mn0);
            float p2 = __expf(sf[j][2] - mn1);
            float p3 = __expf(sf[j][3] - mn1);
            sf[j][0] = p0; sf[j][1] = p1; sf[j][2] = p2; sf[j][3] = p3;
            s0 += p0 + p1; s1 += p2 + p3;
        }
        #pragma unroll
        for (int o = 1; o < 4; o <<= 1) {
            s0 += __shfl_xor_sync(0xffffffffu, s0, o);
            s1 += __shfl_xor_sync(0xffffffffu, s1, o);
        }
        lsum[0] = lsum[0] * alpha0 + s0;
        lsum[1] = lsum[1] * alpha1 + s1;
        #pragma unroll
        for (int j = 0; j < 8; j++) {
            acc[j][0] *= alpha0; acc[j][1] *= alpha0;
            acc[j][2] *= alpha1; acc[j][3] *= alpha1;
        }

        // ---- store P (hi/lo split once) ----
        #pragma unroll
        for (int j = 0; j < 8; j++) {
            int c0 = j * 8 + tg * 2;
            uint32_t h, l;
            tfsplit(sf[j][0], h, l);
            PH[prow * SLD + c0] = __uint_as_float(h); PL[prow * SLD + c0] = __uint_as_float(l);
            tfsplit(sf[j][1], h, l);
            PH[prow * SLD + c0 + 1] = __uint_as_float(h); PL[prow * SLD + c0 + 1] = __uint_as_float(l);
            tfsplit(sf[j][2], h, l);
            PH[(prow + 8) * SLD + c0] = __uint_as_float(h); PL[(prow + 8) * SLD + c0] = __uint_as_float(l);
            tfsplit(sf[j][3], h, l);
            PH[(prow + 8) * SLD + c0 + 1] = __uint_as_float(h); PL[(prow + 8) * SLD + c0 + 1] = __uint_as_float(l);
        }
        __syncwarp();   // P rows are warp-local; cross-lane visibility only

        // ---- acc += P @ V (3xtf32) ----
        #pragma unroll
        for (int ks = 0; ks < 8; ks++) {
            int kc = ks * 8 + tg;
            const float* ph = PH + prow * SLD;
            const float* pl = PL + prow * SLD;
            uint32_t ah0 = __float_as_uint(ph[kc]);
            uint32_t ah1 = __float_as_uint(ph[8 * SLD + kc]);
            uint32_t ah2 = __float_as_uint(ph[kc + 4]);
            uint32_t ah3 = __float_as_uint(ph[8 * SLD + kc + 4]);
            uint32_t al0 = __float_as_uint(pl[kc]);
            uint32_t al1 = __float_as_uint(pl[8 * SLD + kc]);
            uint32_t al2 = __float_as_uint(pl[kc + 4]);
            uint32_t al3 = __float_as_uint(pl[8 * SLD + kc + 4]);
            #pragma unroll
            for (int j = 0; j < 8; j++) {
                const float* vh = VH + (j * 8 + g) * SLD;
                const float* vl = VL + (j * 8 + g) * SLD;
                uint32_t bh0 = __float_as_uint(vh[kc]);
                uint32_t bh1 = __float_as_uint(vh[kc + 4]);
                uint32_t bl0 = __float_as_uint(vl[kc]);
                uint32_t bl1 = __float_as_uint(vl[kc + 4]);
                MMA_TF32(acc[j], ah0, ah1, ah2, ah3, bh0, bh1);
                MMA_TF32(acc[j], al0, al1, al2, al3, bh0, bh1);
                MMA_TF32(acc[j], ah0, ah1, ah2, ah3, bl0, bl1);
            }
        }
        __syncwarp();
    }

    // ---- output ----
    float inv0 = 1.f / lsum[0], inv1 = 1.f / lsum[1];
    int t0 = b * Sc + q0 + prow, t1 = t0 + 8;
    #pragma unroll
    for (int j = 0; j < 8; j++) {
        int col = hId * DVc + j * 8 + tg * 2;
        g_attn[(size_t)t0 * Hc + col]     = acc[j][0] * inv0;
        g_attn[(size_t)t0 * Hc + col + 1] = acc[j][1] * inv0;
        g_attn[(size_t)t1 * Hc + col]     = acc[j][2] * inv1;
        g_attn[(size_t)t1 * Hc + col + 1] = acc[j][3] * inv1;
    }
}

// ---------------- gating ----------------
__global__ void zero_cnt_kernel() { if (threadIdx.x < Ec) g_cnt[threadIdx.x] = 0; }

__global__ void gate_kernel(const float* __restrict__ gw)
{
    int t = blockIdx.x, tid = threadIdx.x;
    int w = tid >> 5, lane = tid & 31;
    const float* xrow = &g_x[(size_t)t * Hc];
    const float* grow = gw + (size_t)w * Hc;
    float s = 0.f;
    for (int k = lane; k < Hc; k += 32) s += xrow[k] * grow[k];
    s = warpsum(s);
    __shared__ float logit[Ec];
    if (lane == 0) logit[w] = s;
    __syncthreads();
    if (tid == 0) {
        float mx = -1e30f;
        for (int e = 0; e < Ec; e++) mx = fmaxf(mx, logit[e]);
        float ex[Ec];
        for (int e = 0; e < Ec; e++) ex[e] = expf(logit[e] - mx);
        int i0 = 0;
        for (int e = 1; e < Ec; e++) if (ex[e] > ex[i0]) i0 = e;
        int i1 = (i0 == 0) ? 1 : 0;
        for (int e = 0; e < Ec; e++) if (e != i0 && ex[e] > ex[i1]) i1 = e;
        float p0 = ex[i0], p1 = ex[i1], tsum = p0 + p1;
        g_topw[t * 2]     = p0 / tsum;
        g_topw[t * 2 + 1] = p1 / tsum;
        int pos0 = atomicAdd(&g_cnt[i0], 1);
        g_list[i0 * Tc + pos0] = t * 2;
        int pos1 = atomicAdd(&g_cnt[i1], 1);
        g_list[i1 * Tc + pos1] = t * 2 + 1;
    }
}

__global__ void combine_kernel()
{
    int i = blockIdx.x * 256 + threadIdx.x;
    int t = i / Hc, j = i - t * Hc;
    g_h[i] += g_eo[(size_t)(t * 2) * Hc + j] + g_eo[(size_t)(t * 2 + 1) * Hc + j];
}

__global__ void final_kernel(const float* __restrict__ fw, const float* __restrict__ hw,
                             const float* __restrict__ hb, float* __restrict__ out)
{
    int b = blockIdx.x, tid = threadIdx.x;
    int t = b * Sc + (Sc - 1);
    const float* row = &g_h[(size_t)t * Hc];
    __shared__ float sred[256];
    float ss = 0.f;
    for (int j = tid; j < Hc; j += 256) { float v = row[j]; ss += v * v; }
    sred[tid] = ss; __syncthreads();
    for (int o = 128; o; o >>= 1) { if (tid < o) sred[tid] += sred[tid + o]; __syncthreads(); }
    float inv = rsqrtf(sred[0] / Hc + 1e-6f);
    __syncthreads();
    float acc = 0.f;
    for (int j = tid; j < Hc; j += 256) acc += row[j] * inv * fw[j] * hw[j];
    sred[tid] = acc; __syncthreads();
    for (int o = 128; o; o >>= 1) { if (tid < o) sred[tid] += sred[tid + o]; __syncthreads(); }
    if (tid == 0) out[b] = sred[0] + hb[0];
}

// ---------------- host launch ----------------
#define SMEM_SINGLE (2 * (ASZ_W + 64  * LDW) * 4)   // 36864 B
#define SMEM_DUAL   (2 * (ASZ_W + 128 * LDW) * 4)   // 55296 B

static inline void tc_dense(const float* A, const float* Bw, const float* bias, float* C,
                            int M, int N, int Kd, int accum)
{
    dim3 grid((N + 63) / 64, M / 64, 1);
    mma_gemm_kernel<0><<<grid, 128, SMEM_SINGLE>>>(A, Bw, nullptr, bias, C, M, N, Kd, accum);
}

extern "C" void kernel_launch(void* const* d_in, const int* in_sizes, int n_in,
                              void* d_out, int out_size)
{
    const float* inputs   = (const float*)d_in[0];
    const float* in_w     = (const float*)d_in[1];
    const float* in_b     = (const float*)d_in[2];
    const float* attn_nw  = (const float*)d_in[3];
    const float* wq       = (const float*)d_in[4];
    const float* wkva     = (const float*)d_in[5];
    const float* kvn_w    = (const float*)d_in[6];
    const float* wkvb     = (const float*)d_in[7];
    const float* wo       = (const float*)d_in[8];
    const float* moe_nw   = (const float*)d_in[9];
    const float* gate_w   = (const float*)d_in[10];
    const float* e_w1     = (const float*)d_in[11];
    const float* e_w2     = (const float*)d_in[12];
    const float* e_w3     = (const float*)d_in[13];
    const float* s_w1     = (const float*)d_in[14];
    const float* s_w2     = (const float*)d_in[15];
    const float* s_w3     = (const float*)d_in[16];
    const float* final_nw = (const float*)d_in[17];
    const float* head_w   = (const float*)d_in[18];
    const float* head_b   = (const float*)d_in[19];
    float* out = (float*)d_out;

    float *h_p, *x_p, *q_p, *kva_p, *ckv_p, *kv_p, *attn_p, *t1_p, *mg_p, *eo_p;
    cudaGetSymbolAddress((void**)&h_p,    g_h);
    cudaGetSymbolAddress((void**)&x_p,    g_x);
    cudaGetSymbolAddress((void**)&q_p,    g_q);
    cudaGetSymbolAddress((void**)&kva_p,  g_kva);
    cudaGetSymbolAddress((void**)&ckv_p,  g_ckv);
    cudaGetSymbolAddress((void**)&kv_p,   g_kv);
    cudaGetSymbolAddress((void**)&attn_p, g_attn);
    cudaGetSymbolAddress((void**)&t1_p,   g_t1);
    cudaGetSymbolAddress((void**)&mg_p,   g_mg);
    cudaGetSymbolAddress((void**)&eo_p,   g_eo);

    cudaFuncSetAttribute(mma_gemm_kernel<0>, cudaFuncAttributeMaxDynamicSharedMemorySize, SMEM_SINGLE);
    cudaFuncSetAttribute(mma_gemm_kernel<1>, cudaFuncAttributeMaxDynamicSharedMemorySize, SMEM_DUAL);
    cudaFuncSetAttribute(mma_gemm_kernel<2>, cudaFuncAttributeMaxDynamicSharedMemorySize, SMEM_DUAL);
    cudaFuncSetAttribute(mma_gemm_kernel<3>, cudaFuncAttributeMaxDynamicSharedMemorySize, SMEM_SINGLE);
    cudaFuncSetAttribute(attn_kernel, cudaFuncAttributeMaxDynamicSharedMemorySize, ATTN_SMEM);

    // embed: h = inputs @ in_w^T + in_b   (K=64)
    tc_dense(inputs, in_w, in_b, h_p, Tc, Hc, 64, 0);

    for (int l = 0; l < Lc; l++) {
        const float* anw   = attn_nw + (size_t)l * Hc;
        const float* wq_l  = wq      + (size_t)l * Hc * Hc;
        const float* wva_l = wkva    + (size_t)l * KVAW * Hc;
        const float* kvn_l = kvn_w   + (size_t)l * Rc;
        const float* wvb_l = wkvb    + (size_t)l * (NHc * KVD) * Rc;
        const float* wo_l  = wo      + (size_t)l * Hc * Hc;
        const float* mnw   = moe_nw  + (size_t)l * Hc;
        const float* gw_l  = gate_w  + (size_t)l * Ec * Hc;
        const float* w1_l  = e_w1    + (size_t)l * Ec * Ic * Hc;
        const float* w2_l  = e_w2    + (size_t)l * Ec * Hc * Ic;
        const float* w3_l  = e_w3    + (size_t)l * Ec * Ic * Hc;
        const float* sw1_l = s_w1    + (size_t)l * SIc * Hc;
        const float* sw2_l = s_w2    + (size_t)l * Hc * SIc;
        const float* sw3_l = s_w3    + (size_t)l * SIc * Hc;

        // attention
        rms_kernel<<<Tc, 256>>>(h_p, Hc, anw, x_p, Hc, Hc);
        tc_dense(x_p, wq_l,  nullptr, q_p,   Tc, Hc,   Hc, 0);
        tc_dense(x_p, wva_l, nullptr, kva_p, Tc, KVAW, Hc, 0);
        rope_kernel<<<Tc, 256>>>();
        rms_kernel<<<Tc, 256>>>(kva_p, KVAW, kvn_l, ckv_p, Rc, Rc);
        tc_dense(ckv_p, wvb_l, nullptr, kv_p, Tc, NHc * KVD, Rc, 0);
        {
            dim3 grid(Sc / 64, NHc, Bc);
            attn_kernel<<<grid, 128, ATTN_SMEM>>>();
        }
        tc_dense(attn_p, wo_l, nullptr, h_p, Tc, Hc, Hc, 1);

        // MoE
        rms_kernel<<<Tc, 256>>>(h_p, Hc, mnw, x_p, Hc, Hc);
        zero_cnt_kernel<<<1, 32>>>();
        gate_kernel<<<Tc, 256>>>(gw_l);
        {
            dim3 g1(Ic / 64, Tc / 64, Ec);
            mma_gemm_kernel<2><<<g1, 128, SMEM_DUAL>>>(x_p, w1_l, w3_l, nullptr, mg_p, Tc, Ic, Hc, 0);
            dim3 g2(Hc / 64, Tc / 64, Ec);
            mma_gemm_kernel<3><<<g2, 128, SMEM_SINGLE>>>(mg_p, w2_l, nullptr, nullptr, eo_p, Tc, Hc, Ic, 0);
            combine_kernel<<<(Tc * Hc) / 256, 256>>>();
        }
        // shared FFN
        {
            dim3 gd(SIc / 64, Tc / 64, 1);
            mma_gemm_kernel<1><<<gd, 128, SMEM_DUAL>>>(x_p, sw1_l, sw3_l, nullptr, t1_p, Tc, SIc, Hc, 0);
        }
        tc_dense(t1_p, sw2_l, nullptr, h_p, Tc, Hc, SIc, 1);
    }

    final_kernel<<<Bc, 256>>>(final_nw, head_w, head_b, out);
}

// round 12
// speedup vs baseline: 1.0685x; 1.0006x over previous
#include <cuda_runtime.h>
#include <math.h>
#include <stdint.h>

// ---------------- model constants ----------------
#define Lc   12
#define Hc   768
#define NHc  12
#define DNc  32
#define DRc  32
#define DVc  64
#define Rc   512
#define Ec   8
#define KTOP 2
#define Ic   256
#define SIc  1024
#define Bc   2
#define Sc   512
#define Tc   (Bc*Sc)
#define QD   (DNc+DRc)        // 64
#define KVD  (DNc+DVc)        // 96
#define KVAW (Rc+DRc)         // 544

// ---------------- scratch (device globals, no allocation) ----------------
__device__ float g_h   [Tc*Hc];
__device__ float g_x   [Tc*Hc];
__device__ float g_q   [Tc*(NHc*QD)];
__device__ float g_kva [Tc*KVAW];
__device__ float g_ckv [Tc*Rc];
__device__ float g_kv  [Tc*(NHc*KVD)];
__device__ float g_attn[Tc*Hc];
__device__ float g_t1  [Tc*SIc];
__device__ float g_mg  [Ec*Tc*Ic];
__device__ float g_eo  [Tc*2*Hc];
__device__ int   g_list[Ec*Tc];
__device__ int   g_cnt [Ec];
__device__ float g_topw[Tc*KTOP];

// ---------------- helpers ----------------
__device__ __forceinline__ float warpsum(float v) {
    #pragma unroll
    for (int o = 16; o; o >>= 1) v += __shfl_down_sync(0xffffffffu, v, o);
    return v;
}

__device__ __forceinline__ uint32_t f2tf(float x) {
    uint32_t u;
    asm("cvt.rna.tf32.f32 %0, %1;" : "=r"(u) : "f"(x));
    return u;
}
__device__ __forceinline__ void tfsplit(float x, uint32_t& hi, uint32_t& lo) {
    hi = f2tf(x);
    lo = f2tf(x - __uint_as_float(hi));
}
__device__ __forceinline__ void split4(float4 v, float4& hi, float4& lo) {
    hi.x = __uint_as_float(f2tf(v.x)); lo.x = __uint_as_float(f2tf(v.x - hi.x));
    hi.y = __uint_as_float(f2tf(v.y)); lo.y = __uint_as_float(f2tf(v.y - hi.y));
    hi.z = __uint_as_float(f2tf(v.z)); lo.z = __uint_as_float(f2tf(v.z - hi.z));
    hi.w = __uint_as_float(f2tf(v.w)); lo.w = __uint_as_float(f2tf(v.w - hi.w));
}

__device__ __forceinline__ uint32_t smem_u32(const void* p) {
    uint32_t a;
    asm("{ .reg .u64 t; cvta.to.shared.u64 t, %1; cvt.u32.u64 %0, t; }" : "=r"(a) : "l"(p));
    return a;
}

#define MMA_TF32(d, a0, a1, a2, a3, b0, b1) \
    asm volatile("mma.sync.aligned.m16n8k8.row.col.f32.tf32.tf32.f32 " \
        "{%0,%1,%2,%3}, {%4,%5,%6,%7}, {%8,%9}, {%0,%1,%2,%3};" \
        : "+f"((d)[0]), "+f"((d)[1]), "+f"((d)[2]), "+f"((d)[3]) \
        : "r"(a0), "r"(a1), "r"(a2), "r"(a3), "r"(b0), "r"(b1))

#define CP_ASYNC16(dst, src, sz) \
    asm volatile("cp.async.cg.shared.global [%0], [%1], 16, %2;" \
        :: "r"(dst), "l"(src), "r"(sz) : "memory")
#define CP_COMMIT asm volatile("cp.async.commit_group;" ::: "memory")
#define CP_WAIT(n) asm volatile("cp.async.wait_group %0;" :: "n"(n) : "memory")

// ---------------- tensor-core 3xtf32 GEMM (64x64 CTA tile, 128 thr) — R6 best ------
#define LDW  36
#define ASZ_W (64*LDW)

template<int MODE>
__global__ __launch_bounds__(128) void mma_gemm_kernel(
    const float* __restrict__ A, const float* __restrict__ B1w,
    const float* __restrict__ B3w, const float* __restrict__ bias,
    float* __restrict__ C, int M, int N, int Kd, int accum)
{
    constexpr bool DUAL  = (MODE == 1 || MODE == 2);
    constexpr int  BROWS = DUAL ? 128 : 64;
    constexpr int  BSZ_W = BROWS * LDW;

    int tid = threadIdx.x;
    int wid = tid >> 5, lane = tid & 31;
    int g = lane >> 2, tg = lane & 3;
    int warpM = wid & 1, warpN = wid >> 1;

    int e   = (MODE >= 2) ? blockIdx.z : 0;
    int cnt = (MODE >= 2) ? g_cnt[e] : M;
    int row0 = blockIdx.y * 64;
    if (row0 >= cnt) return;
    int col0 = blockIdx.x * 64;

    const float* Ap  = A;
    const float* B1p = B1w;
    const float* B3p = B3w;
    float* Cp = C;
    if (MODE == 2) {
        B1p = B1w + (size_t)e * Ic * Hc;
        B3p = B3w + (size_t)e * Ic * Hc;
        Cp  = C + (size_t)e * Tc * Ic;
    }
    if (MODE == 3) {
        Ap  = A + (size_t)e * Tc * Ic;
        B1p = B1w + (size_t)e * Hc * Ic;
    }

    extern __shared__ float dsm[];
    __shared__ int s_tok[64];

    if (MODE == 2) {
        if (tid < 64) {
            int grow = row0 + tid;
            int tok2 = (grow < cnt) ? g_list[e * Tc + grow] : 0;
            s_tok[tid] = tok2 >> 1;
        }
        __syncthreads();
    }

    uint32_t sbase = smem_u32(dsm);
    int lc4 = tid & 7;
    int lrb = tid >> 3;

    int nchunks = Kd / 32;

    auto issue_chunk = [&](int ch, int buf) {
        int c0 = ch * 32 + lc4 * 4;
        uint32_t sA = sbase + (uint32_t)(buf * ASZ_W) * 4u;
        uint32_t sB = sbase + (uint32_t)(2 * ASZ_W + buf * BSZ_W) * 4u;
        #pragma unroll
        for (int i = 0; i < 4; i++) {
            int r = lrb + i * 16;
            const float* src = (MODE == 2) ? &g_x[(size_t)s_tok[r] * Hc + c0]
                                           : Ap + (size_t)(row0 + r) * Kd + c0;
            CP_ASYNC16(sA + (uint32_t)(r * LDW + lc4 * 4) * 4u, src, 16);
        }
        #pragma unroll
        for (int i = 0; i < (DUAL ? 8 : 4); i++) {
            int r = lrb + i * 16;
            int gn; const float* base;
            if (!DUAL) { gn = col0 + r; base = B1p; }
            else if (r < 64) { gn = col0 + r; base = B1p; }
            else { gn = col0 + r - 64; base = B3p; }
            int ok = (gn < N) ? 16 : 0;
            const float* src = base + (size_t)(ok ? gn : 0) * Kd + c0;
            CP_ASYNC16(sB + (uint32_t)(r * LDW + lc4 * 4) * 4u, src, ok);
        }
        CP_COMMIT;
    };

    issue_chunk(0, 0);
    if (nchunks > 1) issue_chunk(1, 1);

    float d1[2][4][4];
    float d3[DUAL ? 2 : 1][DUAL ? 4 : 1][4];
    #pragma unroll
    for (int m = 0; m < 2; m++)
        #pragma unroll
        for (int j = 0; j < 4; j++)
            #pragma unroll
            for (int q = 0; q < 4; q++) {
                d1[m][j][q] = 0.f;
                if (DUAL) d3[m][j][q] = 0.f;
            }

    for (int c = 0; c < nchunks; c++) {
        if (c + 2 <= nchunks) { CP_WAIT(1); } else { CP_WAIT(0); }
        __syncthreads();

        const float* Ab  = dsm + (c & 1) * ASZ_W + (warpM * 32) * LDW;
        const float* Bb  = dsm + 2 * ASZ_W + (c & 1) * BSZ_W + (warpN * 32) * LDW;
        const float* Bb3 = Bb + 64 * LDW;

        #pragma unroll
        for (int ks = 0; ks < 4; ks++) {
            int kc = ks * 8 + tg;
            uint32_t ahi[2][4], alo[2][4];
            #pragma unroll
            for (int m = 0; m < 2; m++) {
                const float* ap = Ab + (m * 16 + g) * LDW;
                tfsplit(ap[kc],               ahi[m][0], alo[m][0]);
                tfsplit(ap[8 * LDW + kc],     ahi[m][1], alo[m][1]);
                tfsplit(ap[kc + 4],           ahi[m][2], alo[m][2]);
                tfsplit(ap[8 * LDW + kc + 4], ahi[m][3], alo[m][3]);
            }
            #pragma unroll
            for (int j = 0; j < 4; j++) {
                const float* bp = Bb + (j * 8 + g) * LDW;
                uint32_t bh0, bl0, bh1, bl1;
                tfsplit(bp[kc],     bh0, bl0);
                tfsplit(bp[kc + 4], bh1, bl1);
                #pragma unroll
                for (int m = 0; m < 2; m++) {
                    MMA_TF32(d1[m][j], ahi[m][0], ahi[m][1], ahi[m][2], ahi[m][3], bh0, bh1);
                    MMA_TF32(d1[m][j], alo[m][0], alo[m][1], alo[m][2], alo[m][3], bh0, bh1);
                    MMA_TF32(d1[m][j], ahi[m][0], ahi[m][1], ahi[m][2], ahi[m][3], bl0, bl1);
                }
            }
            if (DUAL) {
                #pragma unroll
                for (int j = 0; j < 4; j++) {
                    const float* bp = Bb3 + (j * 8 + g) * LDW;
                    uint32_t bh0, bl0, bh1, bl1;
                    tfsplit(bp[kc],     bh0, bl0);
                    tfsplit(bp[kc + 4], bh1, bl1);
                    #pragma unroll
                    for (int m = 0; m < 2; m++) {
                        MMA_TF32(d3[m][j], ahi[m][0], ahi[m][1], ahi[m][2], ahi[m][3], bh0, bh1);
                        MMA_TF32(d3[m][j], alo[m][0], alo[m][1], alo[m][2], alo[m][3], bh0, bh1);
                        MMA_TF32(d3[m][j], ahi[m][0], ahi[m][1], ahi[m][2], ahi[m][3], bl0, bl1);
                    }
                }
            }
        }
        __syncthreads();
        if (c + 2 < nchunks) issue_chunk(c + 2, c & 1);
    }

    int rbase = row0 + warpM * 32;
    int cbase = col0 + warpN * 32;

    #pragma unroll
    for (int m = 0; m < 2; m++) {
        #pragma unroll
        for (int j = 0; j < 4; j++) {
            int col = cbase + j * 8 + tg * 2;
            #pragma unroll
            for (int half = 0; half < 2; half++) {
                int r = rbase + m * 16 + g + half * 8;
                float v0 = d1[m][j][half * 2 + 0];
                float v1 = d1[m][j][half * 2 + 1];
                if (DUAL) {
                    float w0 = d3[m][j][half * 2 + 0];
                    float w1 = d3[m][j][half * 2 + 1];
                    v0 = (v0 / (1.f + __expf(-v0))) * w0;
                    v1 = (v1 / (1.f + __expf(-v1))) * w1;
                }
                if (MODE == 0) {
                    if (r < M && col < N) {
                        size_t o = (size_t)r * N + col;
                        if (bias) { v0 += bias[col]; v1 += bias[col + 1]; }
                        if (accum) { C[o] += v0; C[o + 1] += v1; }
                        else       { C[o] = v0;  C[o + 1] = v1; }
                    }
                } else if (MODE == 1) {
                    size_t o = (size_t)r * N + col;
                    C[o] = v0; C[o + 1] = v1;
                } else if (MODE == 2) {
                    if (r < cnt) {
                        size_t o = (size_t)r * Ic + col;
                        Cp[o] = v0; Cp[o + 1] = v1;
                    }
                } else {
                    if (r < cnt) {
                        int tok2 = g_list[e * Tc + r];
                        float wgt = g_topw[tok2];
                        size_t o = (size_t)tok2 * Hc + col;
                        C[o] = v0 * wgt; C[o + 1] = v1 * wgt;
                    }
                }
            }
        }
    }
}

// ---------------- RMSNorm ----------------
__global__ void rms_kernel(const float* __restrict__ in, int instride,
                           const float* __restrict__ w,
                           float* __restrict__ out, int outstride, int n)
{
    int t = blockIdx.x, tid = threadIdx.x;
    const float* row = in + (size_t)t * instride;
    __shared__ float sred[256];
    float ss = 0.f;
    for (int j = tid; j < n; j += 256) { float v = row[j]; ss += v * v; }
    sred[tid] = ss; __syncthreads();
    for (int o = 128; o; o >>= 1) { if (tid < o) sred[tid] += sred[tid + o]; __syncthreads(); }
    float inv = rsqrtf(sred[0] / n + 1e-6f);
    float* orow = out + (size_t)t * outstride;
    for (int j = tid; j < n; j += 256) orow[j] = row[j] * inv * w[j];
}

// ---------------- RoPE ----------------
__global__ void rope_kernel()
{
    int t = blockIdx.x;
    int pos = t % Sc;
    int tid = threadIdx.x;
    int vec = tid >> 4, i = tid & 15;
    if (vec >= NHc + 1) return;
    float* base = (vec < NHc) ? &g_q[(size_t)t * (NHc * QD) + vec * QD + DNc]
                              : &g_kva[(size_t)t * KVAW + Rc];
    int j1 = i, j2 = i + 16;
    float f1 = powf(10000.0f, -(float)(2 * j1) / 64.0f);
    float f2 = powf(10000.0f, -(float)(2 * j2) / 64.0f);
    float s1, c1, s2, c2;
    sincosf(pos * f1, &s1, &c1);
    sincosf(pos * f2, &s2, &c2);
    float x1 = base[j1], x2 = base[j2];
    base[j1] = x1 * c1 - x2 * s1;
    base[j2] = x2 * c2 + x1 * s2;
}

// ---------------- flash attention on tensor cores (3xtf32) ----------------
// Block per (qtile 64, head, batch), 128 thr / 4 warps; warp tile 16 q-rows x 64.
#define SLD 68
#define ATTN_SMEM (8 * 64 * SLD * 4)

__global__ __launch_bounds__(128) void attn_kernel()
{
    int qt  = (int)gridDim.x - 1 - (int)blockIdx.x;
    int hId = blockIdx.y, b = blockIdx.z;
    int tid = threadIdx.x;
    int wid = tid >> 5, lane = tid & 31;
    int g = lane >> 2, tg = lane & 3;
    int lr = tid >> 1, half = tid & 1;

    extern __shared__ float sm[];
    float* QH = sm;
    float* QL = sm + 1 * 64 * SLD;
    float* KH = sm + 2 * 64 * SLD;
    float* KL = sm + 3 * 64 * SLD;
    float* VH = sm + 4 * 64 * SLD;
    float* VL = sm + 5 * 64 * SLD;
    float* PH = sm + 6 * 64 * SLD;
    float* PL = sm + 7 * 64 * SLD;

    int q0 = qt * 64;

    // load Q tile (rows q-local, cols d), split once
    {
        const float* qrow = &g_q[(size_t)(b * Sc + q0 + lr) * (NHc * QD) + hId * QD + half * 32];
        #pragma unroll
        for (int i = 0; i < 8; i++) {
            float4 v = *(const float4*)(qrow + i * 4);
            float4 hi, lo; split4(v, hi, lo);
            int c = half * 32 + i * 4;
            *(float4*)&QH[lr * SLD + c] = hi;
            *(float4*)&QL[lr * SLD + c] = lo;
        }
    }

    float mrow[2] = { -1e30f, -1e30f };
    float lsum[2] = { 0.f, 0.f };
    float acc[8][4];
    #pragma unroll
    for (int j = 0; j < 8; j++)
        #pragma unroll
        for (int q = 0; q < 4; q++) acc[j][q] = 0.f;

    int prow = wid * 16 + g;   // local q row (first of pair)

    for (int kt = 0; kt <= qt; kt++) {
        __syncthreads();
        // load K tile rows [key][d] and V transposed [dv][key], split
        {
            int kg = b * Sc + kt * 64 + lr;
            const float* src = (half == 0) ? &g_kv [(size_t)kg * (NHc * KVD) + hId * KVD]
                                           : &g_kva[(size_t)kg * KVAW + Rc];
            #pragma unroll
            for (int i = 0; i < 8; i++) {
                float4 v = *(const float4*)(src + i * 4);
                float4 hi, lo; split4(v, hi, lo);
                int c = half * 32 + i * 4;
                *(float4*)&KH[lr * SLD + c] = hi;
                *(float4*)&KL[lr * SLD + c] = lo;
            }
            const float* vp = &g_kv[(size_t)kg * (NHc * KVD) + hId * KVD + DNc + half * 32];
            #pragma unroll
            for (int i = 0; i < 8; i++) {
                float4 v = *(const float4*)(vp + i * 4);
                float4 hi, lo; split4(v, hi, lo);
                int dv = half * 32 + i * 4;
                VH[(dv + 0) * SLD + lr] = hi.x; VL[(dv + 0) * SLD + lr] = lo.x;
                VH[(dv + 1) * SLD + lr] = hi.y; VL[(dv + 1) * SLD + lr] = lo.y;
                VH[(dv + 2) * SLD + lr] = hi.z; VL[(dv + 2) * SLD + lr] = lo.z;
                VH[(dv + 3) * SLD + lr] = hi.w; VL[(dv + 3) * SLD + lr] = lo.w;
            }
        }
        __syncthreads();

        // ---- S = Q @ K^T (3xtf32) ----
        float sf[8][4];
        #pragma unroll
        for (int j = 0; j < 8; j++)
            #pragma unroll
            for (int q = 0; q < 4; q++) sf[j][q] = 0.f;

        #pragma unroll
        for (int ks = 0; ks < 8; ks++) {
            int kc = ks * 8 + tg;
            const float* qh = QH + prow * SLD;
            const float* ql = QL + prow * SLD;
            uint32_t ah0 = __float_as_uint(qh[kc]);
            uint32_t ah1 = __float_as_uint(qh[8 * SLD + kc]);
            uint32_t ah2 = __float_as_uint(qh[kc + 4]);
            uint32_t ah3 = __float_as_uint(qh[8 * SLD + kc + 4]);
            uint32_t al0 = __float_as_uint(ql[kc]);
            uint32_t al1 = __float_as_uint(ql[8 * SLD + kc]);
            uint32_t al2 = __float_as_uint(ql[kc + 4]);
            uint32_t al3 = __float_as_uint(ql[8 * SLD + kc + 4]);
            #pragma unroll
            for (int j = 0; j < 8; j++) {
                const float* kh = KH + (j * 8 + g) * SLD;
                const float* kl = KL + (j * 8 + g) * SLD;
                uint32_t bh0 = __float_as_uint(kh[kc]);
                uint32_t bh1 = __float_as_uint(kh[kc + 4]);
                uint32_t bl0 = __float_as_uint(kl[kc]);
                uint32_t bl1 = __float_as_uint(kl[kc + 4]);
                MMA_TF32(sf[j], ah0, ah1, ah2, ah3, bh0, bh1);
                MMA_TF32(sf[j], al0, al1, al2, al3, bh0, bh1);
                MMA_TF32(sf[j], ah0, ah1, ah2, ah3, bl0, bl1);
            }
        }

        // ---- scale + causal mask ----
        int qrow0 = q0 + prow, qrow1 = qrow0 + 8;
        #pragma unroll
        for (int j = 0; j < 8; j++) {
            int k0 = kt * 64 + j * 8 + tg * 2;
            sf[j][0] = (k0     <= qrow0) ? sf[j][0] * 0.125f : -1e30f;
            sf[j][1] = (k0 + 1 <= qrow0) ? sf[j][1] * 0.125f : -1e30f;
            sf[j][2] = (k0     <= qrow1) ? sf[j][2] * 0.125f : -1e30f;
            sf[j][3] = (k0 + 1 <= qrow1) ? sf[j][3] * 0.125f : -1e30f;
        }

        // ---- online softmax (rows warp-local; reduce over tg lanes) ----
        float mx0 = -1e30f, mx1 = -1e30f;
        #pragma unroll
        for (int j = 0; j < 8; j++) {
            mx0 = fmaxf(mx0, fmaxf(sf[j][0], sf[j][1]));
            mx1 = fmaxf(mx1, fmaxf(sf[j][2], sf[j][3]));
        }
        #pragma unroll
        for (int o = 1; o < 4; o <<= 1) {
            mx0 = fmaxf(mx0, __shfl_xor_sync(0xffffffffu, mx0, o));
            mx1 = fmaxf(mx1, __shfl_xor_sync(0xffffffffu, mx1, o));
        }
        float mn0 = fmaxf(mrow[0], mx0), mn1 = fmaxf(mrow[1], mx1);
        float alpha0 = __expf(mrow[0] - mn0), alpha1 = __expf(mrow[1] - mn1);
        mrow[0] = mn0; mrow[1] = mn1;

        float s0 = 0.f, s1 = 0.f;
        #pragma unroll
        for (int j = 0; j < 8; j++) {
            float p0 = __expf(sf[j][0] - mn0);
            float p1 = __expf(sf[j][1] - mn0);
            float p2 = __expf(sf[j][2] - mn1);
            float p3 = __expf(sf[j][3] - mn1);
            sf[j][0] = p0; sf[j][1] = p1; sf[j][2] = p2; sf[j][3] = p3;
            s0 += p0 + p1; s1 += p2 + p3;
        }
        #pragma unroll
        for (int o = 1; o < 4; o <<= 1) {
            s0 += __shfl_xor_sync(0xffffffffu, s0, o);
            s1 += __shfl_xor_sync(0xffffffffu, s1, o);
        }
        lsum[0] = lsum[0] * alpha0 + s0;
        lsum[1] = lsum[1] * alpha1 + s1;
        #pragma unroll
        for (int j = 0; j < 8; j++) {
            acc[j][0] *= alpha0; acc[j][1] *= alpha0;
            acc[j][2] *= alpha1; acc[j][3] *= alpha1;
        }

        // ---- store P (hi/lo split once) ----
        #pragma unroll
        for (int j = 0; j < 8; j++) {
            int c0 = j * 8 + tg * 2;
            uint32_t h, l;
            tfsplit(sf[j][0], h, l);
            PH[prow * SLD + c0] = __uint_as_float(h); PL[prow * SLD + c0] = __uint_as_float(l);
            tfsplit(sf[j][1], h, l);
            PH[prow * SLD + c0 + 1] = __uint_as_float(h); PL[prow * SLD + c0 + 1] = __uint_as_float(l);
            tfsplit(sf[j][2], h, l);
            PH[(prow + 8) * SLD + c0] = __uint_as_float(h); PL[(prow + 8) * SLD + c0] = __uint_as_float(l);
            tfsplit(sf[j][3], h, l);
            PH[(prow + 8) * SLD + c0 + 1] = __uint_as_float(h); PL[(prow + 8) * SLD + c0 + 1] = __uint_as_float(l);
        }
        __syncwarp();   // P rows are warp-local; cross-lane visibility only

        // ---- acc += P @ V (3xtf32) ----
        #pragma unroll
        for (int ks = 0; ks < 8; ks++) {
            int kc = ks * 8 + tg;
            const float* ph = PH + prow * SLD;
            const float* pl = PL + prow * SLD;
            uint32_t ah0 = __float_as_uint(ph[kc]);
            uint32_t ah1 = __float_as_uint(ph[8 * SLD + kc]);
            uint32_t ah2 = __float_as_uint(ph[kc + 4]);
            uint32_t ah3 = __float_as_uint(ph[8 * SLD + kc + 4]);
            uint32_t al0 = __float_as_uint(pl[kc]);
            uint32_t al1 = __float_as_uint(pl[8 * SLD + kc]);
            uint32_t al2 = __float_as_uint(pl[kc + 4]);
            uint32_t al3 = __float_as_uint(pl[8 * SLD + kc + 4]);
            #pragma unroll
            for (int j = 0; j < 8; j++) {
                const float* vh = VH + (j * 8 + g) * SLD;
                const float* vl = VL + (j * 8 + g) * SLD;
                uint32_t bh0 = __float_as_uint(vh[kc]);
                uint32_t bh1 = __float_as_uint(vh[kc + 4]);
                uint32_t bl0 = __float_as_uint(vl[kc]);
                uint32_t bl1 = __float_as_uint(vl[kc + 4]);
                MMA_TF32(acc[j], ah0, ah1, ah2, ah3, bh0, bh1);
                MMA_TF32(acc[j], al0, al1, al2, al3, bh0, bh1);
                MMA_TF32(acc[j], ah0, ah1, ah2, ah3, bl0, bl1);
            }
        }
        __syncwarp();
    }

    // ---- output ----
    float inv0 = 1.f / lsum[0], inv1 = 1.f / lsum[1];
    int t0 = b * Sc + q0 + prow, t1 = t0 + 8;
    #pragma unroll
    for (int j = 0; j < 8; j++) {
        int col = hId * DVc + j * 8 + tg * 2;
        g_attn[(size_t)t0 * Hc + col]     = acc[j][0] * inv0;
        g_attn[(size_t)t0 * Hc + col + 1] = acc[j][1] * inv0;
        g_attn[(size_t)t1 * Hc + col]     = acc[j][2] * inv1;
        g_attn[(size_t)t1 * Hc + col + 1] = acc[j][3] * inv1;
    }
}

// ---------------- gating ----------------
__global__ void zero_cnt_kernel() { if (threadIdx.x < Ec) g_cnt[threadIdx.x] = 0; }

__global__ void gate_kernel(const float* __restrict__ gw)
{
    int t = blockIdx.x, tid = threadIdx.x;
    int w = tid >> 5, lane = tid & 31;
    const float* xrow = &g_x[(size_t)t * Hc];
    const float* grow = gw + (size_t)w * Hc;
    float s = 0.f;
    for (int k = lane; k < Hc; k += 32) s += xrow[k] * grow[k];
    s = warpsum(s);
    __shared__ float logit[Ec];
    if (lane == 0) logit[w] = s;
    __syncthreads();
    if (tid == 0) {
        float mx = -1e30f;
        for (int e = 0; e < Ec; e++) mx = fmaxf(mx, logit[e]);
        float ex[Ec];
        for (int e = 0; e < Ec; e++) ex[e] = expf(logit[e] - mx);
        int i0 = 0;
        for (int e = 1; e < Ec; e++) if (ex[e] > ex[i0]) i0 = e;
        int i1 = (i0 == 0) ? 1 : 0;
        for (int e = 0; e < Ec; e++) if (e != i0 && ex[e] > ex[i1]) i1 = e;
        float p0 = ex[i0], p1 = ex[i1], tsum = p0 + p1;
        g_topw[t * 2]     = p0 / tsum;
        g_topw[t * 2 + 1] = p1 / tsum;
        int pos0 = atomicAdd(&g_cnt[i0], 1);
        g_list[i0 * Tc + pos0] = t * 2;
        int pos1 = atomicAdd(&g_cnt[i1], 1);
        g_list[i1 * Tc + pos1] = t * 2 + 1;
    }
}

__global__ void combine_kernel()
{
    int i = blockIdx.x * 256 + threadIdx.x;
    int t = i / Hc, j = i - t * Hc;
    g_h[i] += g_eo[(size_t)(t * 2) * Hc + j] + g_eo[(size_t)(t * 2 + 1) * Hc + j];
}

__global__ void final_kernel(const float* __restrict__ fw, const float* __restrict__ hw,
                             const float* __restrict__ hb, float* __restrict__ out)
{
    int b = blockIdx.x, tid = threadIdx.x;
    int t = b * Sc + (Sc - 1);
    const float* row = &g_h[(size_t)t * Hc];
    __shared__ float sred[256];
    float ss = 0.f;
    for (int j = tid; j < Hc; j += 256) { float v = row[j]; ss += v * v; }
    sred[tid] = ss; __syncthreads();
    for (int o = 128; o; o >>= 1) { if (tid < o) sred[tid] += sred[tid + o]; __syncthreads(); }
    float inv = rsqrtf(sred[0] / Hc + 1e-6f);
    __syncthreads();
    float acc = 0.f;
    for (int j = tid; j < Hc; j += 256) acc += row[j] * inv * fw[j] * hw[j];
    sred[tid] = acc; __syncthreads();
    for (int o = 128; o; o >>= 1) { if (tid < o) sred[tid] += sred[tid + o]; __syncthreads(); }
    if (tid == 0) out[b] = sred[0] + hb[0];
}

// ---------------- host launch ----------------
#define SMEM_SINGLE (2 * (ASZ_W + 64  * LDW) * 4)   // 36864 B
#define SMEM_DUAL   (2 * (ASZ_W + 128 * LDW) * 4)   // 55296 B

static inline void tc_dense(const float* A, const float* Bw, const float* bias, float* C,
                            int M, int N, int Kd, int accum)
{
    dim3 grid((N + 63) / 64, M / 64, 1);
    mma_gemm_kernel<0><<<grid, 128, SMEM_SINGLE>>>(A, Bw, nullptr, bias, C, M, N, Kd, accum);
}

extern "C" void kernel_launch(void* const* d_in, const int* in_sizes, int n_in,
                              void* d_out, int out_size)
{
    const float* inputs   = (const float*)d_in[0];
    const float* in_w     = (const float*)d_in[1];
    const float* in_b     = (const float*)d_in[2];
    const float* attn_nw  = (const float*)d_in[3];
    const float* wq       = (const float*)d_in[4];
    const float* wkva     = (const float*)d_in[5];
    const float* kvn_w    = (const float*)d_in[6];
    const float* wkvb     = (const float*)d_in[7];
    const float* wo       = (const float*)d_in[8];
    const float* moe_nw   = (const float*)d_in[9];
    const float* gate_w   = (const float*)d_in[10];
    const float* e_w1     = (const float*)d_in[11];
    const float* e_w2     = (const float*)d_in[12];
    const float* e_w3     = (const float*)d_in[13];
    const float* s_w1     = (const float*)d_in[14];
    const float* s_w2     = (const float*)d_in[15];
    const float* s_w3     = (const float*)d_in[16];
    const float* final_nw = (const float*)d_in[17];
    const float* head_w   = (const float*)d_in[18];
    const float* head_b   = (const float*)d_in[19];
    float* out = (float*)d_out;

    float *h_p, *x_p, *q_p, *kva_p, *ckv_p, *kv_p, *attn_p, *t1_p, *mg_p, *eo_p;
    cudaGetSymbolAddress((void**)&h_p,    g_h);
    cudaGetSymbolAddress((void**)&x_p,    g_x);
    cudaGetSymbolAddress((void**)&q_p,    g_q);
    cudaGetSymbolAddress((void**)&kva_p,  g_kva);
    cudaGetSymbolAddress((void**)&ckv_p,  g_ckv);
    cudaGetSymbolAddress((void**)&kv_p,   g_kv);
    cudaGetSymbolAddress((void**)&attn_p, g_attn);
    cudaGetSymbolAddress((void**)&t1_p,   g_t1);
    cudaGetSymbolAddress((void**)&mg_p,   g_mg);
    cudaGetSymbolAddress((void**)&eo_p,   g_eo);

    cudaFuncSetAttribute(mma_gemm_kernel<0>, cudaFuncAttributeMaxDynamicSharedMemorySize, SMEM_SINGLE);
    cudaFuncSetAttribute(mma_gemm_kernel<1>, cudaFuncAttributeMaxDynamicSharedMemorySize, SMEM_DUAL);
    cudaFuncSetAttribute(mma_gemm_kernel<2>, cudaFuncAttributeMaxDynamicSharedMemorySize, SMEM_DUAL);
    cudaFuncSetAttribute(mma_gemm_kernel<3>, cudaFuncAttributeMaxDynamicSharedMemorySize, SMEM_SINGLE);
    cudaFuncSetAttribute(attn_kernel, cudaFuncAttributeMaxDynamicSharedMemorySize, ATTN_SMEM);

    // embed: h = inputs @ in_w^T + in_b   (K=64)
    tc_dense(inputs, in_w, in_b, h_p, Tc, Hc, 64, 0);

    for (int l = 0; l < Lc; l++) {
        const float* anw   = attn_nw + (size_t)l * Hc;
        const float* wq_l  = wq      + (size_t)l * Hc * Hc;
        const float* wva_l = wkva    + (size_t)l * KVAW * Hc;
        const float* kvn_l = kvn_w   + (size_t)l * Rc;
        const float* wvb_l = wkvb    + (size_t)l * (NHc * KVD) * Rc;
        const float* wo_l  = wo      + (size_t)l * Hc * Hc;
        const float* mnw   = moe_nw  + (size_t)l * Hc;
        const float* gw_l  = gate_w  + (size_t)l * Ec * Hc;
        const float* w1_l  = e_w1    + (size_t)l * Ec * Ic * Hc;
        const float* w2_l  = e_w2    + (size_t)l * Ec * Hc * Ic;
        const float* w3_l  = e_w3    + (size_t)l * Ec * Ic * Hc;
        const float* sw1_l = s_w1    + (size_t)l * SIc * Hc;
        const float* sw2_l = s_w2    + (size_t)l * Hc * SIc;
        const float* sw3_l = s_w3    + (size_t)l * SIc * Hc;

        // attention
        rms_kernel<<<Tc, 256>>>(h_p, Hc, anw, x_p, Hc, Hc);
        tc_dense(x_p, wq_l,  nullptr, q_p,   Tc, Hc,   Hc, 0);
        tc_dense(x_p, wva_l, nullptr, kva_p, Tc, KVAW, Hc, 0);
        rope_kernel<<<Tc, 256>>>();
        rms_kernel<<<Tc, 256>>>(kva_p, KVAW, kvn_l, ckv_p, Rc, Rc);
        tc_dense(ckv_p, wvb_l, nullptr, kv_p, Tc, NHc * KVD, Rc, 0);
        {
            dim3 grid(Sc / 64, NHc, Bc);
            attn_kernel<<<grid, 128, ATTN_SMEM>>>();
        }
        tc_dense(attn_p, wo_l, nullptr, h_p, Tc, Hc, Hc, 1);

        // MoE
        rms_kernel<<<Tc, 256>>>(h_p, Hc, mnw, x_p, Hc, Hc);
        zero_cnt_kernel<<<1, 32>>>();
        gate_kernel<<<Tc, 256>>>(gw_l);
        {
            dim3 g1(Ic / 64, Tc / 64, Ec);
            mma_gemm_kernel<2><<<g1, 128, SMEM_DUAL>>>(x_p, w1_l, w3_l, nullptr, mg_p, Tc, Ic, Hc, 0);
            dim3 g2(Hc / 64, Tc / 64, Ec);
            mma_gemm_kernel<3><<<g2, 128, SMEM_SINGLE>>>(mg_p, w2_l, nullptr, nullptr, eo_p, Tc, Hc, Ic, 0);
            combine_kernel<<<(Tc * Hc) / 256, 256>>>();
        }
        // shared FFN
        {
            dim3 gd(SIc / 64, Tc / 64, 1);
            mma_gemm_kernel<1><<<gd, 128, SMEM_DUAL>>>(x_p, sw1_l, sw3_l, nullptr, t1_p, Tc, SIc, Hc, 0);
        }
        tc_dense(t1_p, sw2_l, nullptr, h_p, Tc, Hc, SIc, 1);
    }

    final_kernel<<<Bc, 256>>>(final_nw, head_w, head_b, out);
}